// round 6
// baseline (speedup 1.0000x reference)
#include <cuda_runtime.h>
#include <cuda_bf16.h>
#include <math.h>
#include <stdint.h>

#define TT 8
#define FIN 128
#define HH 128
#define NMAX 50048
#define G4 (4*HH)

// ---------------- device scratch (allocation-free rule: __device__ globals) ----
static __device__ __nv_bfloat16 g_xh[(size_t)TT * NMAX * HH];
static __device__ __nv_bfloat16 g_xl[(size_t)TT * NMAX * HH];
static __device__ __nv_bfloat16 g_fh[(size_t)TT * NMAX * HH];   // feats hi
static __device__ __nv_bfloat16 g_fl[(size_t)TT * NMAX * HH];   // feats lo
static __device__ __nv_bfloat16 g_b2h[(size_t)TT * NMAX * HH];  // gcn layer1 out hi
static __device__ __nv_bfloat16 g_b2l[(size_t)TT * NMAX * HH];
static __device__ float g_nis[(size_t)TT * NMAX];               // deg then deg^{-1/2}
static __device__ float g_hlin[(size_t)TT * NMAX * HH];         // batched x@W+b
static __device__ float g_agg[(size_t)TT * NMAX * HH];          // batched scatter acc
static __device__ float g_pre[(size_t)TT * NMAX * G4];          // feats@Wih1^T + b (all t)
static __device__ float g_hbuf[(size_t)2 * NMAX * HH];          // fp32 h ping-pong (B bufs)
static __device__ float g_state[(size_t)4 * NMAX * HH];         // h1a,c1,h2a,c2
static __device__ __nv_bfloat16 g_h1h_a[(size_t)NMAX * HH];
static __device__ __nv_bfloat16 g_h1l_a[(size_t)NMAX * HH];
static __device__ __nv_bfloat16 g_h1h_b[(size_t)NMAX * HH];
static __device__ __nv_bfloat16 g_h1l_b[(size_t)NMAX * HH];
static __device__ __nv_bfloat16 g_h2h_a[(size_t)NMAX * HH];
static __device__ __nv_bfloat16 g_h2l_a[(size_t)NMAX * HH];
static __device__ __nv_bfloat16 g_h2h_b[(size_t)NMAX * HH];
static __device__ __nv_bfloat16 g_h2l_b[(size_t)NMAX * HH];
// LSTM weights, gate-interleaved cols [n'=4j+g][k], K-major:
static __device__ __nv_bfloat16 g_B1ih[512 * 128];              // Wih1 planes
static __device__ __nv_bfloat16 g_B1il[512 * 128];
static __device__ __nv_bfloat16 g_B1rh[512 * 128];              // Whh1 planes
static __device__ __nv_bfloat16 g_B1rl[512 * 128];
static __device__ __nv_bfloat16 g_B2h[512 * 256];               // [Wih2 ; Whh2]
static __device__ __nv_bfloat16 g_B2l[512 * 256];
static __device__ __nv_bfloat16 g_GW1h[128 * 128];              // gcn W^T [n][k]
static __device__ __nv_bfloat16 g_GW1l[128 * 128];
static __device__ __nv_bfloat16 g_GW2h[128 * 128];
static __device__ __nv_bfloat16 g_GW2l[128 * 128];
static __device__ float g_bias1[G4];
static __device__ float g_bias2[G4];
static __device__ int   g_idx64;

// ---------------- helpers ----------------
__device__ __forceinline__ int load_idx(const void* p, size_t off) {
    return g_idx64 ? (int)((const long long*)p)[off] : ((const int*)p)[off];
}
__device__ __forceinline__ float sigm(float x) { return 1.0f / (1.0f + expf(-x)); }

__device__ __forceinline__ void split_bf16(float v, __nv_bfloat16& h, __nv_bfloat16& l) {
    h = __float2bfloat16(v);
    l = __float2bfloat16(v - __bfloat162float(h));
}

__device__ __forceinline__ void cpasync16(uint32_t dst, const void* src, int sz) {
    asm volatile("cp.async.cg.shared.global [%0], [%1], 16, %2;\n" :: "r"(dst), "l"(src), "r"(sz));
}
__device__ __forceinline__ void cp_commit() { asm volatile("cp.async.commit_group;\n"); }
__device__ __forceinline__ void cp_wait1() { asm volatile("cp.async.wait_group 1;\n"); }

__device__ __forceinline__ uint32_t swz(uint32_t o) { return o ^ ((o >> 3) & 0x10); }

__device__ __forceinline__ void ldsm4(uint32_t* r, uint32_t addr) {
    asm volatile("ldmatrix.sync.aligned.m8n8.x4.shared.b16 {%0,%1,%2,%3}, [%4];"
                 : "=r"(r[0]), "=r"(r[1]), "=r"(r[2]), "=r"(r[3]) : "r"(addr));
}

__device__ __forceinline__ void mma_bf16(float* d, const uint32_t* a, const uint32_t* b) {
    asm volatile(
        "mma.sync.aligned.m16n8k16.row.col.f32.bf16.bf16.f32 "
        "{%0,%1,%2,%3}, {%4,%5,%6,%7}, {%8,%9}, {%0,%1,%2,%3};\n"
        : "+f"(d[0]), "+f"(d[1]), "+f"(d[2]), "+f"(d[3])
        : "r"(a[0]), "r"(a[1]), "r"(a[2]), "r"(a[3]), "r"(b[0]), "r"(b[1]));
}

// ---------------- prep kernels ----------------
__global__ void detect_idx_kernel(const void* ei) {
    const int* p = (const int*)ei;
    int s = 0;
    for (int i = 1; i < 257; i += 2) s |= p[i];
    g_idx64 = (s == 0) ? 1 : 0;
}

__global__ void split_x_kernel(const float* __restrict__ x, size_t total) {
    for (size_t i = (size_t)blockIdx.x * blockDim.x + threadIdx.x; i < total;
         i += (size_t)gridDim.x * blockDim.x) {
        split_bf16(x[i], g_xh[i], g_xl[i]);
    }
}

__global__ void prep_weights_kernel(const float* __restrict__ gw1, const float* __restrict__ gw2,
                                    const float* __restrict__ wih1, const float* __restrict__ whh1,
                                    const float* __restrict__ bih1, const float* __restrict__ bhh1,
                                    const float* __restrict__ wih2, const float* __restrict__ whh2,
                                    const float* __restrict__ bih2, const float* __restrict__ bhh2) {
    int idx = blockIdx.x * blockDim.x + threadIdx.x;
    if (idx < 512 * 256) {
        int n = idx >> 8;       // gate-interleaved col 4j+g
        int k = idx & 255;
        int j = n >> 2, g = n & 3;
        int orow = g * 128 + j;
        float v2 = (k < 128) ? wih2[orow * 128 + k] : whh2[orow * 128 + (k - 128)];
        split_bf16(v2, g_B2h[idx], g_B2l[idx]);
    }
    if (idx < 512 * 128) {
        int n = idx >> 7;
        int k = idx & 127;
        int j = n >> 2, g = n & 3;
        int orow = g * 128 + j;
        split_bf16(wih1[orow * 128 + k], g_B1ih[idx], g_B1il[idx]);
        split_bf16(whh1[orow * 128 + k], g_B1rh[idx], g_B1rl[idx]);
    }
    if (idx < 128 * 128) {
        int n = idx >> 7, k = idx & 127;
        split_bf16(gw1[k * 128 + n], g_GW1h[idx], g_GW1l[idx]);
        split_bf16(gw2[k * 128 + n], g_GW2h[idx], g_GW2l[idx]);
    }
    if (idx < 512) {
        int j = idx >> 2, g = idx & 3;
        int orow = g * 128 + j;
        g_bias1[idx] = bih1[orow] + bhh1[orow];
        g_bias2[idx] = bih2[orow] + bhh2[orow];
    }
}

// ---------------- GCN scatter (batched over t) ----------------
__global__ void deg_all_kernel(const void* __restrict__ ei, int E, int N, float* __restrict__ deg) {
    long long i = (long long)blockIdx.x * blockDim.x + threadIdx.x;
    if (i >= (long long)TT * E) return;
    int t = (int)(i / E);
    int e = (int)(i - (long long)t * E);
    int d = load_idx(ei, (size_t)t * 2 * E + E + e);
    atomicAdd(&deg[(size_t)t * N + d], 1.0f);
}

__global__ void nis_all_kernel(float* __restrict__ nis, long long total) {
    long long i = (long long)blockIdx.x * blockDim.x + threadIdx.x;
    if (i < total) nis[i] = rsqrtf(nis[i] + 1.0f);
}

// warp per (t, edge): gather h[src] 512B, scale, vector-atomic scatter
__global__ void edge_all_kernel(const void* __restrict__ ei, int E, int N,
                                const float* __restrict__ nis, const float* __restrict__ h,
                                float* __restrict__ agg) {
    long long gw = ((long long)blockIdx.x * blockDim.x + threadIdx.x) >> 5;
    int lane = threadIdx.x & 31;
    if (gw >= (long long)TT * E) return;
    int t = (int)(gw / E);
    int e = (int)(gw - (long long)t * E);
    size_t srcOff = (size_t)t * 2 * E;
    int s = load_idx(ei, srcOff + e);
    int d = load_idx(ei, srcOff + E + e);
    const float* nst = nis + (size_t)t * N;
    float coeff = nst[s] * nst[d];
    const float* ht = h + (size_t)t * N * HH;
    float* at = agg + (size_t)t * N * HH;
    float4 v = ((const float4*)(ht + (size_t)s * HH))[lane];
    v.x *= coeff; v.y *= coeff; v.z *= coeff; v.w *= coeff;
    atomicAdd(((float4*)(at + (size_t)d * HH)) + lane, v);
}

// combine + relu + split (batched over t)
__global__ void combine_all_kernel(const float* __restrict__ agg, const float* __restrict__ hlin,
                                   const float* __restrict__ nis,
                                   __nv_bfloat16* __restrict__ oh, __nv_bfloat16* __restrict__ ol,
                                   long long total) {
    long long idx = (long long)blockIdx.x * blockDim.x + threadIdx.x;
    if (idx >= total) return;
    long long tn = idx >> 7;
    float s = nis[tn];
    float v = fmaxf(agg[idx] + hlin[idx] * s * s, 0.0f);
    split_bf16(v, oh[idx], ol[idx]);
}

// ---------------- emulated-fp32 GEMM via bf16x2 (3-term) tensor mma ----------
// C[M,Nt] = [A1|A2][M,K] @ Bt^T + (Cinit | bias); hi/lo bf16 planes,
// A row-major lda=128 per plane (A2 null -> K<=128); Bt K-major [Nt][K].
// 3-stage cp.async pipeline, one __syncthreads per k-chunk.
#define BM 128
#define BN 128
#define BKK 16
#define STAGEB 16384   // Ah(4K) + Al(4K) + Bh(4K) + Bl(4K) per stage

template<bool LSTM>
__global__ __launch_bounds__(256) void mma_gemm_kernel(
    int M, int Nt, int K,
    const __nv_bfloat16* __restrict__ A1h, const __nv_bfloat16* __restrict__ A1l,
    const __nv_bfloat16* __restrict__ A2h, const __nv_bfloat16* __restrict__ A2l,
    const __nv_bfloat16* __restrict__ Bth, const __nv_bfloat16* __restrict__ Btl,
    const float* __restrict__ bias, const float* __restrict__ Cinit,
    float* __restrict__ Cout, float* __restrict__ cstate,
    float* __restrict__ hout, __nv_bfloat16* __restrict__ houth, __nv_bfloat16* __restrict__ houtl) {

    __shared__ __align__(16) char smemc[3 * STAGEB];   // 48KB
    const uint32_t smemBase = (uint32_t)__cvta_generic_to_shared(smemc);

    const int tid = threadIdx.x;
    const int lane = tid & 31;
    const int wid = tid >> 5;
    const int wm = wid >> 2;          // 0..1
    const int wn = wid & 3;           // 0..3
    const int row0 = blockIdx.y * BM;
    const int col0 = blockIdx.x * BN;

    float acc[4][4][4];
#pragma unroll
    for (int i = 0; i < 4; i++)
#pragma unroll
        for (int j = 0; j < 4; j++)
#pragma unroll
            for (int v = 0; v < 4; v++) acc[i][j][v] = 0.0f;

    const int KT = K / BKK;

    const int lrow = tid >> 1;        // 0..127
    const int lh = tid & 1;
    const uint32_t dOff = swz((uint32_t)(lrow * 32 + lh * 16));

    auto load_tile = [&](int kt, int buf) {
        const int k0 = kt * BKK;
        const __nv_bfloat16 *Aph, *Apl;
        int kk;
        if (k0 < 128) { Aph = A1h; Apl = A1l; kk = k0; }
        else          { Aph = A2h; Apl = A2l; kk = k0 - 128; }
        const uint32_t base = smemBase + buf * STAGEB;
        const int gr = row0 + lrow;
        const int pa = (gr < M) ? 16 : 0;
        const size_t aoff = (size_t)gr * 128 + kk + lh * 8;
        cpasync16(base + dOff,         Aph + aoff, pa);
        cpasync16(base + 4096 + dOff,  Apl + aoff, pa);
        const size_t boff = (size_t)(col0 + lrow) * K + k0 + lh * 8;
        cpasync16(base + 8192 + dOff,  Bth + boff, 16);
        cpasync16(base + 12288 + dOff, Btl + boff, 16);
    };

    const int a_r = lane & 15;
    const int a_h = lane >> 4;
    const int b_n = (lane & 7) + ((lane >> 4) << 3);
    const int b_h = (lane >> 3) & 1;

    load_tile(0, 0);
    cp_commit();
    if (KT > 1) { load_tile(1, 1); }
    cp_commit();

    int buf = 0;
    for (int kt = 0; kt < KT; kt++) {
        cp_wait1();
        __syncthreads();
        const uint32_t base = smemBase + buf * STAGEB;

        uint32_t ah[4][4], al[4][4], bh[4][2], bl[4][2];
#pragma unroll
        for (int mf = 0; mf < 4; mf++) {
            uint32_t ao = swz((uint32_t)((wm * 64 + mf * 16 + a_r) * 32 + a_h * 16));
            ldsm4(ah[mf], base + ao);
            ldsm4(al[mf], base + 4096 + ao);
        }
#pragma unroll
        for (int nf2 = 0; nf2 < 2; nf2++) {
            uint32_t bo = swz((uint32_t)((wn * 32 + nf2 * 16 + b_n) * 32 + b_h * 16));
            uint32_t t4[4];
            ldsm4(t4, base + 8192 + bo);
            bh[2 * nf2][0] = t4[0]; bh[2 * nf2][1] = t4[1];
            bh[2 * nf2 + 1][0] = t4[2]; bh[2 * nf2 + 1][1] = t4[3];
            ldsm4(t4, base + 12288 + bo);
            bl[2 * nf2][0] = t4[0]; bl[2 * nf2][1] = t4[1];
            bl[2 * nf2 + 1][0] = t4[2]; bl[2 * nf2 + 1][1] = t4[3];
        }
#pragma unroll
        for (int mf = 0; mf < 4; mf++)
#pragma unroll
            for (int nf = 0; nf < 4; nf++) {
                mma_bf16(acc[mf][nf], ah[mf], bh[nf]);
                mma_bf16(acc[mf][nf], ah[mf], bl[nf]);
                mma_bf16(acc[mf][nf], al[mf], bh[nf]);
            }

        if (kt + 2 < KT) {
            int nbuf = buf + 2; if (nbuf >= 3) nbuf -= 3;
            load_tile(kt + 2, nbuf);
        }
        cp_commit();
        if (++buf == 3) buf = 0;
    }
    __syncthreads();

    if (!LSTM) {
#pragma unroll
        for (int mf = 0; mf < 4; mf++) {
            int gr = row0 + wm * 64 + mf * 16 + (lane >> 2);
#pragma unroll
            for (int nf = 0; nf < 4; nf++) {
                int gc = col0 + wn * 32 + nf * 8 + 2 * (lane & 3);
                float b0 = bias[gc], b1 = bias[gc + 1];
                if (gr < M) {
                    float2 v = make_float2(acc[mf][nf][0] + b0, acc[mf][nf][1] + b1);
                    *(float2*)(Cout + (size_t)gr * Nt + gc) = v;
                }
                if (gr + 8 < M) {
                    float2 v = make_float2(acc[mf][nf][2] + b0, acc[mf][nf][3] + b1);
                    *(float2*)(Cout + (size_t)(gr + 8) * Nt + gc) = v;
                }
            }
        }
    } else {
        // gate quads interleaved: col 4j+{i,f,g,o}; stage 64-row chunks in smem
        float (*sC)[132] = (float (*)[132])smemc;
        const int j0 = col0 >> 2;
        for (int ch = 0; ch < 2; ch++) {
            __syncthreads();
            if (wm == ch) {
#pragma unroll
                for (int mf = 0; mf < 4; mf++) {
                    int rl = mf * 16 + (lane >> 2);
                    int gr = row0 + ch * 64 + rl;
#pragma unroll
                    for (int nf = 0; nf < 4; nf++) {
                        int cl = wn * 32 + nf * 8 + 2 * (lane & 3);
                        int gc = col0 + cl;
                        float i00, i01, i10, i11;
                        if (Cinit) {
                            size_t r0i = (size_t)gr * G4 + gc;
                            size_t r1i = (size_t)(gr + 8) * G4 + gc;
                            i00 = (gr < M) ? Cinit[r0i] : 0.0f;
                            i01 = (gr < M) ? Cinit[r0i + 1] : 0.0f;
                            i10 = (gr + 8 < M) ? Cinit[r1i] : 0.0f;
                            i11 = (gr + 8 < M) ? Cinit[r1i + 1] : 0.0f;
                        } else {
                            i00 = i10 = bias[gc];
                            i01 = i11 = bias[gc + 1];
                        }
                        sC[rl][cl] = acc[mf][nf][0] + i00;
                        sC[rl][cl + 1] = acc[mf][nf][1] + i01;
                        sC[rl + 8][cl] = acc[mf][nf][2] + i10;
                        sC[rl + 8][cl + 1] = acc[mf][nf][3] + i11;
                    }
                }
            }
            __syncthreads();
            for (int q = tid; q < 64 * 32; q += 256) {
                int rl = q >> 5, jl = q & 31;
                int node = row0 + ch * 64 + rl;
                if (node < M) {
                    float4 g4 = *(float4*)&sC[rl][4 * jl];
                    size_t ci = (size_t)node * HH + j0 + jl;
                    float cn = sigm(g4.y) * cstate[ci] + sigm(g4.x) * tanhf(g4.z);
                    cstate[ci] = cn;
                    float hv = sigm(g4.w) * tanhf(cn);
                    hout[ci] = hv;
                    split_bf16(hv, houth[ci], houtl[ci]);
                }
            }
        }
    }
}

// warp per node: out = h2 . out_w + out_b
__global__ void out_proj_kernel(const float* __restrict__ h2, const float* __restrict__ w,
                                const float* __restrict__ b, float* __restrict__ out, int n) {
    int gw = (blockIdx.x * blockDim.x + threadIdx.x) >> 5;
    int lane = threadIdx.x & 31;
    if (gw >= n) return;
    float4 hv = ((const float4*)(h2 + (size_t)gw * HH))[lane];
    float4 wv = ((const float4*)w)[lane];
    float s = hv.x * wv.x + hv.y * wv.y + hv.z * wv.z + hv.w * wv.w;
#pragma unroll
    for (int off = 16; off; off >>= 1) s += __shfl_xor_sync(0xFFFFFFFFu, s, off);
    if (lane == 0) out[gw] = s + b[0];
}

__global__ void copy_states_kernel(const float* __restrict__ st, float* __restrict__ out, size_t nh) {
    size_t i = (size_t)blockIdx.x * blockDim.x + threadIdx.x;
    size_t total = 4 * nh;
    for (; i < total; i += (size_t)gridDim.x * blockDim.x) out[i] = st[i];
}

// ---------------- host launch ----------------
static inline int cdiv(int a, int b) { return (a + b - 1) / b; }
#define SYM(var, sym) cudaGetSymbolAddress((void**)&var, sym)

extern "C" void kernel_launch(void* const* d_in, const int* in_sizes, int n_in,
                              void* d_out, int out_size) {
    const float* x    = (const float*)d_in[0];
    const void*  ei   = d_in[1];
    const float* gw1  = (const float*)d_in[2];
    const float* gb1  = (const float*)d_in[3];
    const float* gw2  = (const float*)d_in[4];
    const float* gb2  = (const float*)d_in[5];
    const float* wih1 = (const float*)d_in[6];
    const float* whh1 = (const float*)d_in[7];
    const float* bih1 = (const float*)d_in[8];
    const float* bhh1 = (const float*)d_in[9];
    const float* wih2 = (const float*)d_in[10];
    const float* whh2 = (const float*)d_in[11];
    const float* bih2 = (const float*)d_in[12];
    const float* bhh2 = (const float*)d_in[13];
    const float* outw = (const float*)d_in[14];
    const float* outb = (const float*)d_in[15];

    const int N = in_sizes[0] / (TT * FIN);
    const int E = in_sizes[1] / (2 * TT);
    float* out = (float*)d_out;

    __nv_bfloat16 *xh, *xl, *fh, *fl, *b2h, *b2l;
    __nv_bfloat16 *h1h_a, *h1l_a, *h1h_b, *h1l_b, *h2h_a, *h2l_a, *h2h_b, *h2l_b;
    __nv_bfloat16 *B1ih, *B1il, *B1rh, *B1rl, *B2h, *B2l, *GW1h, *GW1l, *GW2h, *GW2l;
    float *nis, *hlin, *agg, *pre, *hbuf, *state, *bias1, *bias2;
    SYM(xh, g_xh); SYM(xl, g_xl); SYM(fh, g_fh); SYM(fl, g_fl);
    SYM(b2h, g_b2h); SYM(b2l, g_b2l);
    SYM(h1h_a, g_h1h_a); SYM(h1l_a, g_h1l_a); SYM(h1h_b, g_h1h_b); SYM(h1l_b, g_h1l_b);
    SYM(h2h_a, g_h2h_a); SYM(h2l_a, g_h2l_a); SYM(h2h_b, g_h2h_b); SYM(h2l_b, g_h2l_b);
    SYM(B1ih, g_B1ih); SYM(B1il, g_B1il); SYM(B1rh, g_B1rh); SYM(B1rl, g_B1rl);
    SYM(B2h, g_B2h); SYM(B2l, g_B2l);
    SYM(GW1h, g_GW1h); SYM(GW1l, g_GW1l); SYM(GW2h, g_GW2h); SYM(GW2l, g_GW2l);
    SYM(nis, g_nis); SYM(hlin, g_hlin); SYM(agg, g_agg); SYM(pre, g_pre);
    SYM(hbuf, g_hbuf); SYM(state, g_state); SYM(bias1, g_bias1); SYM(bias2, g_bias2);

    const size_t NH = (size_t)N * HH;
    const long long TN = (long long)TT * N;
    const long long TNH = TN * HH;

    const int mbA = (int)((TN + BM - 1) / BM);  // 3125
    const int mbL = cdiv(N, BM);                // 391

    // launches 1-4, then the GCN L1 GEMM lands at launch #5 for ncu (-s 5)
    detect_idx_kernel<<<1, 1>>>(ei);                                            // 1
    prep_weights_kernel<<<cdiv(512 * 256, 256), 256>>>(gw1, gw2, wih1, whh1,    // 2
                                                       bih1, bhh1, wih2, whh2, bih2, bhh2);
    split_x_kernel<<<2048, 256>>>(x, (size_t)TN * FIN);                         // 3
    cudaMemsetAsync(nis, 0, TN * sizeof(float));                                // 4

    // -------- GCN layer 1 GEMM (batched over all t) --------                  // 5
    mma_gemm_kernel<false><<<dim3(1, mbA), 256>>>(
        (int)TN, HH, 128, xh, xl, nullptr, nullptr, GW1h, GW1l, gb1, nullptr,
        hlin, nullptr, nullptr, nullptr, nullptr);

    deg_all_kernel<<<(unsigned)(((long long)TT * E + 255) / 256), 256>>>(ei, E, N, nis);
    nis_all_kernel<<<(unsigned)((TN + 255) / 256), 256>>>(nis, TN);

    cudaMemsetAsync(agg, 0, TNH * sizeof(float));
    edge_all_kernel<<<(unsigned)(((long long)TT * E * 32 + 255) / 256), 256>>>(ei, E, N, nis, hlin, agg);
    combine_all_kernel<<<(unsigned)((TNH + 255) / 256), 256>>>(agg, hlin, nis, b2h, b2l, TNH);

    // -------- GCN layer 2 --------
    mma_gemm_kernel<false><<<dim3(1, mbA), 256>>>(
        (int)TN, HH, 128, b2h, b2l, nullptr, nullptr, GW2h, GW2l, gb2, nullptr,
        hlin, nullptr, nullptr, nullptr, nullptr);
    cudaMemsetAsync(agg, 0, TNH * sizeof(float));
    edge_all_kernel<<<(unsigned)(((long long)TT * E * 32 + 255) / 256), 256>>>(ei, E, N, nis, hlin, agg);
    combine_all_kernel<<<(unsigned)((TNH + 255) / 256), 256>>>(agg, hlin, nis, fh, fl, TNH);

    // -------- pre: feats @ Wih1^T + bias1 for ALL t (batched, off critical path)
    mma_gemm_kernel<false><<<dim3(4, mbA), 256>>>(
        (int)TN, G4, 128, fh, fl, nullptr, nullptr, B1ih, B1il, bias1, nullptr,
        pre, nullptr, nullptr, nullptr, nullptr);

    // -------- LSTM over time --------
    cudaMemsetAsync(state, 0, 4 * NH * sizeof(float));
    cudaMemsetAsync(h1h_a, 0, NH * sizeof(__nv_bfloat16));
    cudaMemsetAsync(h1l_a, 0, NH * sizeof(__nv_bfloat16));
    cudaMemsetAsync(h2h_a, 0, NH * sizeof(__nv_bfloat16));
    cudaMemsetAsync(h2l_a, 0, NH * sizeof(__nv_bfloat16));

    float* h1a = state;
    float* c1  = state + NH;
    float* h2a = state + 2 * NH;
    float* c2  = state + 3 * NH;
    float* h1b = hbuf;
    float* h2b = hbuf + NH;

    for (int t = 0; t < TT; t++) {
        const int odd = t & 1;
        const __nv_bfloat16* h1ih = odd ? h1h_b : h1h_a;
        const __nv_bfloat16* h1il = odd ? h1l_b : h1l_a;
        __nv_bfloat16* h1oh = odd ? h1h_a : h1h_b;
        __nv_bfloat16* h1ol = odd ? h1l_a : h1l_b;
        const __nv_bfloat16* h2ih = odd ? h2h_b : h2h_a;
        const __nv_bfloat16* h2il = odd ? h2l_b : h2l_a;
        __nv_bfloat16* h2oh = odd ? h2h_a : h2h_b;
        __nv_bfloat16* h2ol = odd ? h2l_a : h2l_b;
        float* h1_out = odd ? h1a : h1b;
        float* h2_out = odd ? h2a : h2b;

        // layer 1: recurrent half only (K=128) + precomputed input half via Cinit
        mma_gemm_kernel<true><<<dim3(4, mbL), 256>>>(
            N, G4, 128, h1ih, h1il, nullptr, nullptr, B1rh, B1rl,
            bias1, pre + (size_t)t * N * G4, nullptr, c1, h1_out, h1oh, h1ol);
        // layer 2: full K=256 ([h1_t ; h2_{t-1}])
        mma_gemm_kernel<true><<<dim3(4, mbL), 256>>>(
            N, G4, 256, h1oh, h1ol, h2ih, h2il, B2h, B2l,
            bias2, nullptr, nullptr, c2, h2_out, h2oh, h2ol);
        out_proj_kernel<<<cdiv(N * 32, 256), 256>>>(h2_out, outw, outb, out + (size_t)t * N, N);
    }

    // -------- tail: h1, c1, h2, c2 (t=7 odd -> finals in buf A = state) ------
    copy_states_kernel<<<1024, 256>>>(state, out + (size_t)TT * N, NH);
}

// round 7
// speedup vs baseline: 1.0963x; 1.0963x over previous
#include <cuda_runtime.h>
#include <cuda_bf16.h>
#include <math.h>
#include <stdint.h>

#define TT 8
#define FIN 128
#define HH 128
#define NMAX 50048
#define G4 (4*HH)

// ---------------- device scratch (allocation-free rule: __device__ globals) ----
static __device__ __nv_bfloat16 g_xh[(size_t)TT * NMAX * HH];
static __device__ __nv_bfloat16 g_xl[(size_t)TT * NMAX * HH];
static __device__ __nv_bfloat16 g_fh[(size_t)TT * NMAX * HH];   // feats hi
static __device__ __nv_bfloat16 g_fl[(size_t)TT * NMAX * HH];   // feats lo
static __device__ __nv_bfloat16 g_b2h[(size_t)TT * NMAX * HH];  // gcn layer1 out hi
static __device__ __nv_bfloat16 g_b2l[(size_t)TT * NMAX * HH];
static __device__ float g_nis[(size_t)TT * NMAX];               // deg then deg^{-1/2}
static __device__ float g_hlin[(size_t)TT * NMAX * HH];         // batched x@W+b
static __device__ float g_agg[(size_t)TT * NMAX * HH];          // batched scatter acc
static __device__ float g_hbuf[(size_t)2 * NMAX * HH];          // fp32 h2 ping-pong B buf + spare
static __device__ float g_state[(size_t)4 * NMAX * HH];         // h1a,c1,h2a,c2
static __device__ __nv_bfloat16 g_h1h_a[(size_t)NMAX * HH];
static __device__ __nv_bfloat16 g_h1l_a[(size_t)NMAX * HH];
static __device__ __nv_bfloat16 g_h1h_b[(size_t)NMAX * HH];
static __device__ __nv_bfloat16 g_h1l_b[(size_t)NMAX * HH];
static __device__ __nv_bfloat16 g_h2h_a[(size_t)NMAX * HH];
static __device__ __nv_bfloat16 g_h2l_a[(size_t)NMAX * HH];
static __device__ __nv_bfloat16 g_h2h_b[(size_t)NMAX * HH];
static __device__ __nv_bfloat16 g_h2l_b[(size_t)NMAX * HH];
// LSTM weights, gate-interleaved cols [n'=4j+g][k], K-major, K=256 = [Wih ; Whh]
static __device__ __nv_bfloat16 g_B1h[512 * 256];
static __device__ __nv_bfloat16 g_B1l[512 * 256];
static __device__ __nv_bfloat16 g_B2h[512 * 256];
static __device__ __nv_bfloat16 g_B2l[512 * 256];
static __device__ __nv_bfloat16 g_GW1h[128 * 128];              // gcn W^T [n][k]
static __device__ __nv_bfloat16 g_GW1l[128 * 128];
static __device__ __nv_bfloat16 g_GW2h[128 * 128];
static __device__ __nv_bfloat16 g_GW2l[128 * 128];
static __device__ float g_bias1[G4];
static __device__ float g_bias2[G4];
static __device__ int   g_idx64;

// ---------------- helpers ----------------
__device__ __forceinline__ int load_idx(const void* p, size_t off) {
    return g_idx64 ? (int)((const long long*)p)[off] : ((const int*)p)[off];
}
__device__ __forceinline__ float sigm(float x) { return 1.0f / (1.0f + expf(-x)); }

__device__ __forceinline__ void split_bf16(float v, __nv_bfloat16& h, __nv_bfloat16& l) {
    h = __float2bfloat16(v);
    l = __float2bfloat16(v - __bfloat162float(h));
}

__device__ __forceinline__ void cpasync16(uint32_t dst, const void* src, int sz) {
    asm volatile("cp.async.cg.shared.global [%0], [%1], 16, %2;\n" :: "r"(dst), "l"(src), "r"(sz));
}
__device__ __forceinline__ void cp_commit() { asm volatile("cp.async.commit_group;\n"); }
__device__ __forceinline__ void cp_wait1() { asm volatile("cp.async.wait_group 1;\n"); }

__device__ __forceinline__ uint32_t swz(uint32_t o) { return o ^ ((o >> 3) & 0x10); }

__device__ __forceinline__ void ldsm4(uint32_t* r, uint32_t addr) {
    asm volatile("ldmatrix.sync.aligned.m8n8.x4.shared.b16 {%0,%1,%2,%3}, [%4];"
                 : "=r"(r[0]), "=r"(r[1]), "=r"(r[2]), "=r"(r[3]) : "r"(addr));
}

__device__ __forceinline__ void mma_bf16(float* d, const uint32_t* a, const uint32_t* b) {
    asm volatile(
        "mma.sync.aligned.m16n8k16.row.col.f32.bf16.bf16.f32 "
        "{%0,%1,%2,%3}, {%4,%5,%6,%7}, {%8,%9}, {%0,%1,%2,%3};\n"
        : "+f"(d[0]), "+f"(d[1]), "+f"(d[2]), "+f"(d[3])
        : "r"(a[0]), "r"(a[1]), "r"(a[2]), "r"(a[3]), "r"(b[0]), "r"(b[1]));
}

// ---------------- prep kernels ----------------
__global__ void detect_idx_kernel(const void* ei) {
    const int* p = (const int*)ei;
    int s = 0;
    for (int i = 1; i < 257; i += 2) s |= p[i];
    g_idx64 = (s == 0) ? 1 : 0;
}

__global__ void split_x_kernel(const float* __restrict__ x, size_t total) {
    for (size_t i = (size_t)blockIdx.x * blockDim.x + threadIdx.x; i < total;
         i += (size_t)gridDim.x * blockDim.x) {
        split_bf16(x[i], g_xh[i], g_xl[i]);
    }
}

__global__ void prep_weights_kernel(const float* __restrict__ gw1, const float* __restrict__ gw2,
                                    const float* __restrict__ wih1, const float* __restrict__ whh1,
                                    const float* __restrict__ bih1, const float* __restrict__ bhh1,
                                    const float* __restrict__ wih2, const float* __restrict__ whh2,
                                    const float* __restrict__ bih2, const float* __restrict__ bhh2) {
    int idx = blockIdx.x * blockDim.x + threadIdx.x;
    if (idx < 512 * 256) {
        int n = idx >> 8;       // gate-interleaved col 4j+g
        int k = idx & 255;
        int j = n >> 2, g = n & 3;
        int orow = g * 128 + j;
        float v1, v2;
        if (k < 128) { v1 = wih1[orow * 128 + k];         v2 = wih2[orow * 128 + k]; }
        else         { v1 = whh1[orow * 128 + (k - 128)]; v2 = whh2[orow * 128 + (k - 128)]; }
        split_bf16(v1, g_B1h[idx], g_B1l[idx]);
        split_bf16(v2, g_B2h[idx], g_B2l[idx]);
    }
    if (idx < 128 * 128) {
        int n = idx >> 7, k = idx & 127;
        split_bf16(gw1[k * 128 + n], g_GW1h[idx], g_GW1l[idx]);
        split_bf16(gw2[k * 128 + n], g_GW2h[idx], g_GW2l[idx]);
    }
    if (idx < 512) {
        int j = idx >> 2, g = idx & 3;
        int orow = g * 128 + j;
        g_bias1[idx] = bih1[orow] + bhh1[orow];
        g_bias2[idx] = bih2[orow] + bhh2[orow];
    }
}

// ---------------- GCN scatter (batched over t) ----------------
__global__ void deg_all_kernel(const void* __restrict__ ei, int E, int N, float* __restrict__ deg) {
    long long i = (long long)blockIdx.x * blockDim.x + threadIdx.x;
    if (i >= (long long)TT * E) return;
    int t = (int)(i / E);
    int e = (int)(i - (long long)t * E);
    int d = load_idx(ei, (size_t)t * 2 * E + E + e);
    atomicAdd(&deg[(size_t)t * N + d], 1.0f);
}

__global__ void nis_all_kernel(float* __restrict__ nis, long long total) {
    long long i = (long long)blockIdx.x * blockDim.x + threadIdx.x;
    if (i < total) nis[i] = rsqrtf(nis[i] + 1.0f);
}

// warp per (t, edge): gather h[src] 512B, scale, vector-atomic scatter
__global__ void edge_all_kernel(const void* __restrict__ ei, int E, int N,
                                const float* __restrict__ nis, const float* __restrict__ h,
                                float* __restrict__ agg) {
    long long gw = ((long long)blockIdx.x * blockDim.x + threadIdx.x) >> 5;
    int lane = threadIdx.x & 31;
    if (gw >= (long long)TT * E) return;
    int t = (int)(gw / E);
    int e = (int)(gw - (long long)t * E);
    size_t srcOff = (size_t)t * 2 * E;
    int s = load_idx(ei, srcOff + e);
    int d = load_idx(ei, srcOff + E + e);
    const float* nst = nis + (size_t)t * N;
    float coeff = nst[s] * nst[d];
    const float* ht = h + (size_t)t * N * HH;
    float* at = agg + (size_t)t * N * HH;
    float4 v = ((const float4*)(ht + (size_t)s * HH))[lane];
    v.x *= coeff; v.y *= coeff; v.z *= coeff; v.w *= coeff;
    atomicAdd(((float4*)(at + (size_t)d * HH)) + lane, v);
}

// combine + relu + split (batched over t)
__global__ void combine_all_kernel(const float* __restrict__ agg, const float* __restrict__ hlin,
                                   const float* __restrict__ nis,
                                   __nv_bfloat16* __restrict__ oh, __nv_bfloat16* __restrict__ ol,
                                   long long total) {
    long long idx = (long long)blockIdx.x * blockDim.x + threadIdx.x;
    if (idx >= total) return;
    long long tn = idx >> 7;
    float s = nis[tn];
    float v = fmaxf(agg[idx] + hlin[idx] * s * s, 0.0f);
    split_bf16(v, oh[idx], ol[idx]);
}

// ---------------- emulated-fp32 GEMM via bf16x2 (3-term) tensor mma ----------
// C[M,Nt] = [A1|A2][M,K] @ Bt^T + bias; hi/lo bf16 planes, A lda=128/plane
// (A2 null -> K<=128); Bt K-major [Nt][K]. 3-stage cp.async pipeline,
// single __syncthreads per k-chunk, registers uncapped (2 CTAs/SM).
#define BM 128
#define BN 128
#define BKK 16
#define STAGEB 16384   // Ah(4K) + Al(4K) + Bh(4K) + Bl(4K) per stage

template<bool LSTM>
__global__ __launch_bounds__(256) void mma_gemm_kernel(
    int M, int Nt, int K,
    const __nv_bfloat16* __restrict__ A1h, const __nv_bfloat16* __restrict__ A1l,
    const __nv_bfloat16* __restrict__ A2h, const __nv_bfloat16* __restrict__ A2l,
    const __nv_bfloat16* __restrict__ Bth, const __nv_bfloat16* __restrict__ Btl,
    const float* __restrict__ bias,
    float* __restrict__ Cout, float* __restrict__ cstate,
    float* __restrict__ hout, __nv_bfloat16* __restrict__ houth, __nv_bfloat16* __restrict__ houtl) {

    __shared__ __align__(16) char smemc[3 * STAGEB];   // 48KB
    const uint32_t smemBase = (uint32_t)__cvta_generic_to_shared(smemc);

    const int tid = threadIdx.x;
    const int lane = tid & 31;
    const int wid = tid >> 5;
    const int wm = wid >> 2;          // 0..1
    const int wn = wid & 3;           // 0..3
    const int row0 = blockIdx.y * BM;
    const int col0 = blockIdx.x * BN;

    float acc[4][4][4];
#pragma unroll
    for (int i = 0; i < 4; i++)
#pragma unroll
        for (int j = 0; j < 4; j++)
#pragma unroll
            for (int v = 0; v < 4; v++) acc[i][j][v] = 0.0f;

    const int KT = K / BKK;

    const int lrow = tid >> 1;        // 0..127
    const int lh = tid & 1;
    const uint32_t dOff = swz((uint32_t)(lrow * 32 + lh * 16));

    auto load_tile = [&](int kt, int buf) {
        const int k0 = kt * BKK;
        const __nv_bfloat16 *Aph, *Apl;
        int kk;
        if (k0 < 128) { Aph = A1h; Apl = A1l; kk = k0; }
        else          { Aph = A2h; Apl = A2l; kk = k0 - 128; }
        const uint32_t base = smemBase + buf * STAGEB;
        const int gr = row0 + lrow;
        const int pa = (gr < M) ? 16 : 0;
        const size_t aoff = (size_t)gr * 128 + kk + lh * 8;
        cpasync16(base + dOff,         Aph + aoff, pa);
        cpasync16(base + 4096 + dOff,  Apl + aoff, pa);
        const size_t boff = (size_t)(col0 + lrow) * K + k0 + lh * 8;
        cpasync16(base + 8192 + dOff,  Bth + boff, 16);
        cpasync16(base + 12288 + dOff, Btl + boff, 16);
    };

    const int a_r = lane & 15;
    const int a_h = lane >> 4;
    const int b_n = (lane & 7) + ((lane >> 4) << 3);
    const int b_h = (lane >> 3) & 1;

    load_tile(0, 0);
    cp_commit();
    if (KT > 1) { load_tile(1, 1); }
    cp_commit();

    int buf = 0;
    for (int kt = 0; kt < KT; kt++) {
        cp_wait1();
        __syncthreads();
        const uint32_t base = smemBase + buf * STAGEB;

        uint32_t ah[4][4], al[4][4], bh[4][2], bl[4][2];
#pragma unroll
        for (int mf = 0; mf < 4; mf++) {
            uint32_t ao = swz((uint32_t)((wm * 64 + mf * 16 + a_r) * 32 + a_h * 16));
            ldsm4(ah[mf], base + ao);
            ldsm4(al[mf], base + 4096 + ao);
        }
#pragma unroll
        for (int nf2 = 0; nf2 < 2; nf2++) {
            uint32_t bo = swz((uint32_t)((wn * 32 + nf2 * 16 + b_n) * 32 + b_h * 16));
            uint32_t t4[4];
            ldsm4(t4, base + 8192 + bo);
            bh[2 * nf2][0] = t4[0]; bh[2 * nf2][1] = t4[1];
            bh[2 * nf2 + 1][0] = t4[2]; bh[2 * nf2 + 1][1] = t4[3];
            ldsm4(t4, base + 12288 + bo);
            bl[2 * nf2][0] = t4[0]; bl[2 * nf2][1] = t4[1];
            bl[2 * nf2 + 1][0] = t4[2]; bl[2 * nf2 + 1][1] = t4[3];
        }
#pragma unroll
        for (int mf = 0; mf < 4; mf++)
#pragma unroll
            for (int nf = 0; nf < 4; nf++) {
                mma_bf16(acc[mf][nf], ah[mf], bh[nf]);
                mma_bf16(acc[mf][nf], ah[mf], bl[nf]);
                mma_bf16(acc[mf][nf], al[mf], bh[nf]);
            }

        if (kt + 2 < KT) {
            int nbuf = buf + 2; if (nbuf >= 3) nbuf -= 3;
            load_tile(kt + 2, nbuf);
        }
        cp_commit();
        if (++buf == 3) buf = 0;
    }
    __syncthreads();

    if (!LSTM) {
#pragma unroll
        for (int mf = 0; mf < 4; mf++) {
            int gr = row0 + wm * 64 + mf * 16 + (lane >> 2);
#pragma unroll
            for (int nf = 0; nf < 4; nf++) {
                int gc = col0 + wn * 32 + nf * 8 + 2 * (lane & 3);
                float b0 = bias[gc], b1 = bias[gc + 1];
                if (gr < M) {
                    float2 v = make_float2(acc[mf][nf][0] + b0, acc[mf][nf][1] + b1);
                    *(float2*)(Cout + (size_t)gr * Nt + gc) = v;
                }
                if (gr + 8 < M) {
                    float2 v = make_float2(acc[mf][nf][2] + b0, acc[mf][nf][3] + b1);
                    *(float2*)(Cout + (size_t)(gr + 8) * Nt + gc) = v;
                }
            }
        }
    } else {
        // gate quads interleaved: col 4j+{i,f,g,o}; stage 64-row chunks in smem
        float (*sC)[132] = (float (*)[132])smemc;
        const int j0 = col0 >> 2;
        for (int ch = 0; ch < 2; ch++) {
            __syncthreads();
            if (wm == ch) {
#pragma unroll
                for (int mf = 0; mf < 4; mf++) {
                    int rl = mf * 16 + (lane >> 2);
#pragma unroll
                    for (int nf = 0; nf < 4; nf++) {
                        int cl = wn * 32 + nf * 8 + 2 * (lane & 3);
                        float b0 = bias[col0 + cl], b1 = bias[col0 + cl + 1];
                        sC[rl][cl] = acc[mf][nf][0] + b0;
                        sC[rl][cl + 1] = acc[mf][nf][1] + b1;
                        sC[rl + 8][cl] = acc[mf][nf][2] + b0;
                        sC[rl + 8][cl + 1] = acc[mf][nf][3] + b1;
                    }
                }
            }
            __syncthreads();
            for (int q = tid; q < 64 * 32; q += 256) {
                int rl = q >> 5, jl = q & 31;
                int node = row0 + ch * 64 + rl;
                if (node < M) {
                    float4 g4 = *(float4*)&sC[rl][4 * jl];
                    size_t ci = (size_t)node * HH + j0 + jl;
                    float cn = sigm(g4.y) * cstate[ci] + sigm(g4.x) * tanhf(g4.z);
                    cstate[ci] = cn;
                    float hv = sigm(g4.w) * tanhf(cn);
                    if (hout) hout[ci] = hv;
                    split_bf16(hv, houth[ci], houtl[ci]);
                }
            }
        }
    }
}

// warp per node: out = h2 . out_w + out_b
__global__ void out_proj_kernel(const float* __restrict__ h2, const float* __restrict__ w,
                                const float* __restrict__ b, float* __restrict__ out, int n) {
    int gw = (blockIdx.x * blockDim.x + threadIdx.x) >> 5;
    int lane = threadIdx.x & 31;
    if (gw >= n) return;
    float4 hv = ((const float4*)(h2 + (size_t)gw * HH))[lane];
    float4 wv = ((const float4*)w)[lane];
    float s = hv.x * wv.x + hv.y * wv.y + hv.z * wv.z + hv.w * wv.w;
#pragma unroll
    for (int off = 16; off; off >>= 1) s += __shfl_xor_sync(0xFFFFFFFFu, s, off);
    if (lane == 0) out[gw] = s + b[0];
}

__global__ void copy_states_kernel(const float* __restrict__ st, float* __restrict__ out, size_t nh) {
    size_t i = (size_t)blockIdx.x * blockDim.x + threadIdx.x;
    size_t total = 4 * nh;
    for (; i < total; i += (size_t)gridDim.x * blockDim.x) out[i] = st[i];
}

// ---------------- host launch ----------------
static inline int cdiv(int a, int b) { return (a + b - 1) / b; }
#define SYM(var, sym) cudaGetSymbolAddress((void**)&var, sym)

extern "C" void kernel_launch(void* const* d_in, const int* in_sizes, int n_in,
                              void* d_out, int out_size) {
    const float* x    = (const float*)d_in[0];
    const void*  ei   = d_in[1];
    const float* gw1  = (const float*)d_in[2];
    const float* gb1  = (const float*)d_in[3];
    const float* gw2  = (const float*)d_in[4];
    const float* gb2  = (const float*)d_in[5];
    const float* wih1 = (const float*)d_in[6];
    const float* whh1 = (const float*)d_in[7];
    const float* bih1 = (const float*)d_in[8];
    const float* bhh1 = (const float*)d_in[9];
    const float* wih2 = (const float*)d_in[10];
    const float* whh2 = (const float*)d_in[11];
    const float* bih2 = (const float*)d_in[12];
    const float* bhh2 = (const float*)d_in[13];
    const float* outw = (const float*)d_in[14];
    const float* outb = (const float*)d_in[15];

    const int N = in_sizes[0] / (TT * FIN);
    const int E = in_sizes[1] / (2 * TT);
    float* out = (float*)d_out;

    __nv_bfloat16 *xh, *xl, *fh, *fl, *b2h, *b2l;
    __nv_bfloat16 *h1h_a, *h1l_a, *h1h_b, *h1l_b, *h2h_a, *h2l_a, *h2h_b, *h2l_b;
    __nv_bfloat16 *B1h, *B1l, *B2h, *B2l, *GW1h, *GW1l, *GW2h, *GW2l;
    float *nis, *hlin, *agg, *hbuf, *state, *bias1, *bias2;
    SYM(xh, g_xh); SYM(xl, g_xl); SYM(fh, g_fh); SYM(fl, g_fl);
    SYM(b2h, g_b2h); SYM(b2l, g_b2l);
    SYM(h1h_a, g_h1h_a); SYM(h1l_a, g_h1l_a); SYM(h1h_b, g_h1h_b); SYM(h1l_b, g_h1l_b);
    SYM(h2h_a, g_h2h_a); SYM(h2l_a, g_h2l_a); SYM(h2h_b, g_h2h_b); SYM(h2l_b, g_h2l_b);
    SYM(B1h, g_B1h); SYM(B1l, g_B1l); SYM(B2h, g_B2h); SYM(B2l, g_B2l);
    SYM(GW1h, g_GW1h); SYM(GW1l, g_GW1l); SYM(GW2h, g_GW2h); SYM(GW2l, g_GW2l);
    SYM(nis, g_nis); SYM(hlin, g_hlin); SYM(agg, g_agg);
    SYM(hbuf, g_hbuf); SYM(state, g_state); SYM(bias1, g_bias1); SYM(bias2, g_bias2);

    const size_t NH = (size_t)N * HH;
    const long long TN = (long long)TT * N;
    const long long TNH = TN * HH;

    const int mbA = (int)((TN + BM - 1) / BM);  // 3125
    const int mbL = cdiv(N, BM);                // 391

    // launches 1-4, then the GCN L1 GEMM lands at launch #5 for ncu (-s 5)
    detect_idx_kernel<<<1, 1>>>(ei);                                            // 1
    prep_weights_kernel<<<cdiv(512 * 256, 256), 256>>>(gw1, gw2, wih1, whh1,    // 2
                                                       bih1, bhh1, wih2, whh2, bih2, bhh2);
    split_x_kernel<<<2048, 256>>>(x, (size_t)TN * FIN);                         // 3
    cudaMemsetAsync(nis, 0, TN * sizeof(float));                                // 4

    // -------- GCN layer 1 GEMM (batched over all t) --------                  // 5
    mma_gemm_kernel<false><<<dim3(1, mbA), 256>>>(
        (int)TN, HH, 128, xh, xl, nullptr, nullptr, GW1h, GW1l, gb1,
        hlin, nullptr, nullptr, nullptr, nullptr);

    deg_all_kernel<<<(unsigned)(((long long)TT * E + 255) / 256), 256>>>(ei, E, N, nis);
    nis_all_kernel<<<(unsigned)((TN + 255) / 256), 256>>>(nis, TN);

    cudaMemsetAsync(agg, 0, TNH * sizeof(float));
    edge_all_kernel<<<(unsigned)(((long long)TT * E * 32 + 255) / 256), 256>>>(ei, E, N, nis, hlin, agg);
    combine_all_kernel<<<(unsigned)((TNH + 255) / 256), 256>>>(agg, hlin, nis, b2h, b2l, TNH);

    // -------- GCN layer 2 --------
    mma_gemm_kernel<false><<<dim3(1, mbA), 256>>>(
        (int)TN, HH, 128, b2h, b2l, nullptr, nullptr, GW2h, GW2l, gb2,
        hlin, nullptr, nullptr, nullptr, nullptr);
    cudaMemsetAsync(agg, 0, TNH * sizeof(float));
    edge_all_kernel<<<(unsigned)(((long long)TT * E * 32 + 255) / 256), 256>>>(ei, E, N, nis, hlin, agg);
    combine_all_kernel<<<(unsigned)((TNH + 255) / 256), 256>>>(agg, hlin, nis, fh, fl, TNH);

    // -------- LSTM over time (fused gates+cell GEMM, ping-pong h planes) -----
    cudaMemsetAsync(state, 0, 4 * NH * sizeof(float));
    cudaMemsetAsync(h1h_a, 0, NH * sizeof(__nv_bfloat16));
    cudaMemsetAsync(h1l_a, 0, NH * sizeof(__nv_bfloat16));
    cudaMemsetAsync(h2h_a, 0, NH * sizeof(__nv_bfloat16));
    cudaMemsetAsync(h2l_a, 0, NH * sizeof(__nv_bfloat16));

    float* h1a = state;               // final h1 (t=7 odd writes A bufs)
    float* c1  = state + NH;
    float* h2a = state + 2 * NH;
    float* c2  = state + 3 * NH;
    float* h2b = hbuf;                // fp32 h2 for out_proj on even t

    for (int t = 0; t < TT; t++) {
        const int odd = t & 1;
        const __nv_bfloat16* h1ih = odd ? h1h_b : h1h_a;
        const __nv_bfloat16* h1il = odd ? h1l_b : h1l_a;
        __nv_bfloat16* h1oh = odd ? h1h_a : h1h_b;
        __nv_bfloat16* h1ol = odd ? h1l_a : h1l_b;
        const __nv_bfloat16* h2ih = odd ? h2h_b : h2h_a;
        const __nv_bfloat16* h2il = odd ? h2l_b : h2l_a;
        __nv_bfloat16* h2oh = odd ? h2h_a : h2h_b;
        __nv_bfloat16* h2ol = odd ? h2l_a : h2l_b;
        float* h1_out = (t == TT - 1) ? h1a : nullptr;   // fp32 h1 only needed at the end
        float* h2_out = odd ? h2a : h2b;                 // fp32 h2 for out_proj each t

        // layer 1: K=256 [feats_t ; h1_{t-1}]
        mma_gemm_kernel<true><<<dim3(4, mbL), 256>>>(
            N, G4, 256, fh + (size_t)t * NH, fl + (size_t)t * NH, h1ih, h1il,
            B1h, B1l, bias1, nullptr, c1, h1_out, h1oh, h1ol);
        // layer 2: K=256 [h1_t ; h2_{t-1}]
        mma_gemm_kernel<true><<<dim3(4, mbL), 256>>>(
            N, G4, 256, h1oh, h1ol, h2ih, h2il,
            B2h, B2l, bias2, nullptr, c2, h2_out, h2oh, h2ol);
        out_proj_kernel<<<cdiv(N * 32, 256), 256>>>(h2_out, outw, outb, out + (size_t)t * N, N);
    }

    // -------- tail: h1, c1, h2, c2 (t=7 odd -> finals in buf A = state) ------
    copy_states_kernel<<<1024, 256>>>(state, out + (size_t)TT * N, NH);
}

// round 8
// speedup vs baseline: 1.1331x; 1.0335x over previous
#include <cuda_runtime.h>
#include <cuda_bf16.h>
#include <math.h>
#include <stdint.h>

#define TT 8
#define FIN 128
#define HH 128
#define NMAX 50048
#define G4 (4*HH)

// ---------------- device scratch (allocation-free rule: __device__ globals) ----
static __device__ __nv_bfloat16 g_xh[(size_t)TT * NMAX * HH];
static __device__ __nv_bfloat16 g_xl[(size_t)TT * NMAX * HH];
static __device__ __nv_bfloat16 g_fh[(size_t)TT * NMAX * HH];   // feats hi
static __device__ __nv_bfloat16 g_fl[(size_t)TT * NMAX * HH];   // feats lo
static __device__ __nv_bfloat16 g_b2h[(size_t)TT * NMAX * HH];  // gcn layer1 out hi
static __device__ __nv_bfloat16 g_b2l[(size_t)TT * NMAX * HH];
static __device__ float g_nis[(size_t)TT * NMAX];               // deg then deg^{-1/2}
static __device__ float g_hlin[(size_t)TT * NMAX * HH];         // batched x@W+b
static __device__ float g_agg[(size_t)TT * NMAX * HH];          // scatter accumulator
static __device__ float g_hbuf[(size_t)2 * NMAX * HH];          // fp32 h2 B buf + spare
static __device__ float g_state[(size_t)4 * NMAX * HH];         // h1a,c1,h2a,c2
static __device__ __nv_bfloat16 g_h1h_a[(size_t)NMAX * HH];
static __device__ __nv_bfloat16 g_h1l_a[(size_t)NMAX * HH];
static __device__ __nv_bfloat16 g_h1h_b[(size_t)NMAX * HH];
static __device__ __nv_bfloat16 g_h1l_b[(size_t)NMAX * HH];
static __device__ __nv_bfloat16 g_h2h_a[(size_t)NMAX * HH];
static __device__ __nv_bfloat16 g_h2l_a[(size_t)NMAX * HH];
static __device__ __nv_bfloat16 g_h2h_b[(size_t)NMAX * HH];
static __device__ __nv_bfloat16 g_h2l_b[(size_t)NMAX * HH];
// LSTM weights, gate-interleaved cols [n'=4j+g][k], K-major, K=256 = [Wih ; Whh]
static __device__ __nv_bfloat16 g_B1h[512 * 256];
static __device__ __nv_bfloat16 g_B1l[512 * 256];
static __device__ __nv_bfloat16 g_B2h[512 * 256];
static __device__ __nv_bfloat16 g_B2l[512 * 256];
static __device__ __nv_bfloat16 g_GW1h[128 * 128];              // gcn W^T [n][k]
static __device__ __nv_bfloat16 g_GW1l[128 * 128];
static __device__ __nv_bfloat16 g_GW2h[128 * 128];
static __device__ __nv_bfloat16 g_GW2l[128 * 128];
static __device__ float g_bias1[G4];
static __device__ float g_bias2[G4];
static __device__ int   g_idx64;

// ---------------- helpers ----------------
__device__ __forceinline__ int load_idx(const void* p, size_t off) {
    return g_idx64 ? (int)((const long long*)p)[off] : ((const int*)p)[off];
}
__device__ __forceinline__ float sigm(float x) { return 1.0f / (1.0f + expf(-x)); }

__device__ __forceinline__ void split_bf16(float v, __nv_bfloat16& h, __nv_bfloat16& l) {
    h = __float2bfloat16(v);
    l = __float2bfloat16(v - __bfloat162float(h));
}

__device__ __forceinline__ void cpasync16(uint32_t dst, const void* src, int sz) {
    asm volatile("cp.async.cg.shared.global [%0], [%1], 16, %2;\n" :: "r"(dst), "l"(src), "r"(sz));
}
__device__ __forceinline__ void cp_commit() { asm volatile("cp.async.commit_group;\n"); }
__device__ __forceinline__ void cp_wait1() { asm volatile("cp.async.wait_group 1;\n"); }

__device__ __forceinline__ uint32_t swz(uint32_t o) { return o ^ ((o >> 3) & 0x10); }

__device__ __forceinline__ void ldsm4(uint32_t* r, uint32_t addr) {
    asm volatile("ldmatrix.sync.aligned.m8n8.x4.shared.b16 {%0,%1,%2,%3}, [%4];"
                 : "=r"(r[0]), "=r"(r[1]), "=r"(r[2]), "=r"(r[3]) : "r"(addr));
}

__device__ __forceinline__ void mma_bf16(float* d, const uint32_t* a, const uint32_t* b) {
    asm volatile(
        "mma.sync.aligned.m16n8k16.row.col.f32.bf16.bf16.f32 "
        "{%0,%1,%2,%3}, {%4,%5,%6,%7}, {%8,%9}, {%0,%1,%2,%3};\n"
        : "+f"(d[0]), "+f"(d[1]), "+f"(d[2]), "+f"(d[3])
        : "r"(a[0]), "r"(a[1]), "r"(a[2]), "r"(a[3]), "r"(b[0]), "r"(b[1]));
}

// ---------------- prep kernels ----------------
__global__ void detect_idx_kernel(const void* ei) {
    const int* p = (const int*)ei;
    int s = 0;
    for (int i = 1; i < 257; i += 2) s |= p[i];
    g_idx64 = (s == 0) ? 1 : 0;
}

__global__ void split_x_kernel(const float* __restrict__ x, size_t total) {
    for (size_t i = (size_t)blockIdx.x * blockDim.x + threadIdx.x; i < total;
         i += (size_t)gridDim.x * blockDim.x) {
        split_bf16(x[i], g_xh[i], g_xl[i]);
    }
}

__global__ void prep_weights_kernel(const float* __restrict__ gw1, const float* __restrict__ gw2,
                                    const float* __restrict__ wih1, const float* __restrict__ whh1,
                                    const float* __restrict__ bih1, const float* __restrict__ bhh1,
                                    const float* __restrict__ wih2, const float* __restrict__ whh2,
                                    const float* __restrict__ bih2, const float* __restrict__ bhh2) {
    int idx = blockIdx.x * blockDim.x + threadIdx.x;
    if (idx < 512 * 256) {
        int n = idx >> 8;       // gate-interleaved col 4j+g
        int k = idx & 255;
        int j = n >> 2, g = n & 3;
        int orow = g * 128 + j;
        float v1, v2;
        if (k < 128) { v1 = wih1[orow * 128 + k];         v2 = wih2[orow * 128 + k]; }
        else         { v1 = whh1[orow * 128 + (k - 128)]; v2 = whh2[orow * 128 + (k - 128)]; }
        split_bf16(v1, g_B1h[idx], g_B1l[idx]);
        split_bf16(v2, g_B2h[idx], g_B2l[idx]);
    }
    if (idx < 128 * 128) {
        int n = idx >> 7, k = idx & 127;
        split_bf16(gw1[k * 128 + n], g_GW1h[idx], g_GW1l[idx]);
        split_bf16(gw2[k * 128 + n], g_GW2h[idx], g_GW2l[idx]);
    }
    if (idx < 512) {
        int j = idx >> 2, g = idx & 3;
        int orow = g * 128 + j;
        g_bias1[idx] = bih1[orow] + bhh1[orow];
        g_bias2[idx] = bih2[orow] + bhh2[orow];
    }
}

// ---------------- GCN scatter ----------------
// deg/nis batched over t (tiny kernels; atomics on 1.6MB - L2-resident)
__global__ void deg_all_kernel(const void* __restrict__ ei, int E, int N, float* __restrict__ deg) {
    long long i = (long long)blockIdx.x * blockDim.x + threadIdx.x;
    if (i >= (long long)TT * E) return;
    int t = (int)(i / E);
    int e = (int)(i - (long long)t * E);
    int d = load_idx(ei, (size_t)t * 2 * E + E + e);
    atomicAdd(&deg[(size_t)t * N + d], 1.0f);
}

__global__ void nis_all_kernel(float* __restrict__ nis, long long total) {
    long long i = (long long)blockIdx.x * blockDim.x + threadIdx.x;
    if (i < total) nis[i] = rsqrtf(nis[i] + 1.0f);
}

// PER-TIMESTEP edge pass: working set hlin_t+agg_t = 51MB, fits L2.
// warp per edge: gather h[src] 512B contiguous, scale, vector-atomic scatter.
__global__ void edge_msg_kernel(const void* __restrict__ ei, size_t srcOff, size_t dstOff, int E,
                                const float* __restrict__ nis_t, const float* __restrict__ h_t,
                                float* __restrict__ agg_t) {
    int gw = (blockIdx.x * blockDim.x + threadIdx.x) >> 5;
    int lane = threadIdx.x & 31;
    if (gw >= E) return;
    int s = load_idx(ei, srcOff + (size_t)gw);
    int d = load_idx(ei, dstOff + (size_t)gw);
    float coeff = nis_t[s] * nis_t[d];
    float4 v = ((const float4*)(h_t + (size_t)s * HH))[lane];
    v.x *= coeff; v.y *= coeff; v.z *= coeff; v.w *= coeff;
    atomicAdd(((float4*)(agg_t + (size_t)d * HH)) + lane, v);
}

// per-t combine + relu + split
__global__ void gcn_combine_kernel(const float* __restrict__ agg_t, const float* __restrict__ hlin_t,
                                   const float* __restrict__ nis_t,
                                   __nv_bfloat16* __restrict__ oh, __nv_bfloat16* __restrict__ ol,
                                   int n) {
    int idx = blockIdx.x * blockDim.x + threadIdx.x;
    if (idx >= n * HH) return;
    int node = idx >> 7;
    float s = nis_t[node];
    float v = fmaxf(agg_t[idx] + hlin_t[idx] * s * s, 0.0f);
    split_bf16(v, oh[idx], ol[idx]);
}

// ---------------- emulated-fp32 GEMM via bf16x2 (3-term) tensor mma ----------
// C[M,Nt] = [A1|A2][M,K] @ Bt^T + bias; hi/lo bf16 planes, A lda=128/plane
// (A2 null -> K<=128); Bt K-major [Nt][K]. 3-stage cp.async pipeline.
#define BM 128
#define BN 128
#define BKK 16
#define STAGEB 16384   // Ah(4K) + Al(4K) + Bh(4K) + Bl(4K) per stage

template<bool LSTM>
__global__ __launch_bounds__(256) void mma_gemm_kernel(
    int M, int Nt, int K,
    const __nv_bfloat16* __restrict__ A1h, const __nv_bfloat16* __restrict__ A1l,
    const __nv_bfloat16* __restrict__ A2h, const __nv_bfloat16* __restrict__ A2l,
    const __nv_bfloat16* __restrict__ Bth, const __nv_bfloat16* __restrict__ Btl,
    const float* __restrict__ bias,
    float* __restrict__ Cout, float* __restrict__ cstate,
    float* __restrict__ hout, __nv_bfloat16* __restrict__ houth, __nv_bfloat16* __restrict__ houtl) {

    __shared__ __align__(16) char smemc[3 * STAGEB];   // 48KB
    const uint32_t smemBase = (uint32_t)__cvta_generic_to_shared(smemc);

    const int tid = threadIdx.x;
    const int lane = tid & 31;
    const int wid = tid >> 5;
    const int wm = wid >> 2;          // 0..1
    const int wn = wid & 3;           // 0..3
    const int row0 = blockIdx.y * BM;
    const int col0 = blockIdx.x * BN;

    float acc[4][4][4];
#pragma unroll
    for (int i = 0; i < 4; i++)
#pragma unroll
        for (int j = 0; j < 4; j++)
#pragma unroll
            for (int v = 0; v < 4; v++) acc[i][j][v] = 0.0f;

    const int KT = K / BKK;

    const int lrow = tid >> 1;        // 0..127
    const int lh = tid & 1;
    const uint32_t dOff = swz((uint32_t)(lrow * 32 + lh * 16));

    auto load_tile = [&](int kt, int buf) {
        const int k0 = kt * BKK;
        const __nv_bfloat16 *Aph, *Apl;
        int kk;
        if (k0 < 128) { Aph = A1h; Apl = A1l; kk = k0; }
        else          { Aph = A2h; Apl = A2l; kk = k0 - 128; }
        const uint32_t base = smemBase + buf * STAGEB;
        const int gr = row0 + lrow;
        const int pa = (gr < M) ? 16 : 0;
        const size_t aoff = (size_t)gr * 128 + kk + lh * 8;
        cpasync16(base + dOff,         Aph + aoff, pa);
        cpasync16(base + 4096 + dOff,  Apl + aoff, pa);
        const size_t boff = (size_t)(col0 + lrow) * K + k0 + lh * 8;
        cpasync16(base + 8192 + dOff,  Bth + boff, 16);
        cpasync16(base + 12288 + dOff, Btl + boff, 16);
    };

    const int a_r = lane & 15;
    const int a_h = lane >> 4;
    const int b_n = (lane & 7) + ((lane >> 4) << 3);
    const int b_h = (lane >> 3) & 1;

    load_tile(0, 0);
    cp_commit();
    if (KT > 1) { load_tile(1, 1); }
    cp_commit();

    int buf = 0;
    for (int kt = 0; kt < KT; kt++) {
        cp_wait1();
        __syncthreads();
        const uint32_t base = smemBase + buf * STAGEB;

        uint32_t ah[4][4], al[4][4], bh[4][2], bl[4][2];
#pragma unroll
        for (int mf = 0; mf < 4; mf++) {
            uint32_t ao = swz((uint32_t)((wm * 64 + mf * 16 + a_r) * 32 + a_h * 16));
            ldsm4(ah[mf], base + ao);
            ldsm4(al[mf], base + 4096 + ao);
        }
#pragma unroll
        for (int nf2 = 0; nf2 < 2; nf2++) {
            uint32_t bo = swz((uint32_t)((wn * 32 + nf2 * 16 + b_n) * 32 + b_h * 16));
            uint32_t t4[4];
            ldsm4(t4, base + 8192 + bo);
            bh[2 * nf2][0] = t4[0]; bh[2 * nf2][1] = t4[1];
            bh[2 * nf2 + 1][0] = t4[2]; bh[2 * nf2 + 1][1] = t4[3];
            ldsm4(t4, base + 12288 + bo);
            bl[2 * nf2][0] = t4[0]; bl[2 * nf2][1] = t4[1];
            bl[2 * nf2 + 1][0] = t4[2]; bl[2 * nf2 + 1][1] = t4[3];
        }
#pragma unroll
        for (int mf = 0; mf < 4; mf++)
#pragma unroll
            for (int nf = 0; nf < 4; nf++) {
                mma_bf16(acc[mf][nf], ah[mf], bh[nf]);
                mma_bf16(acc[mf][nf], ah[mf], bl[nf]);
                mma_bf16(acc[mf][nf], al[mf], bh[nf]);
            }

        if (kt + 2 < KT) {
            int nbuf = buf + 2; if (nbuf >= 3) nbuf -= 3;
            load_tile(kt + 2, nbuf);
        }
        cp_commit();
        if (++buf == 3) buf = 0;
    }
    __syncthreads();

    if (!LSTM) {
#pragma unroll
        for (int mf = 0; mf < 4; mf++) {
            int gr = row0 + wm * 64 + mf * 16 + (lane >> 2);
#pragma unroll
            for (int nf = 0; nf < 4; nf++) {
                int gc = col0 + wn * 32 + nf * 8 + 2 * (lane & 3);
                float b0 = bias[gc], b1 = bias[gc + 1];
                if (gr < M) {
                    float2 v = make_float2(acc[mf][nf][0] + b0, acc[mf][nf][1] + b1);
                    *(float2*)(Cout + (size_t)gr * Nt + gc) = v;
                }
                if (gr + 8 < M) {
                    float2 v = make_float2(acc[mf][nf][2] + b0, acc[mf][nf][3] + b1);
                    *(float2*)(Cout + (size_t)(gr + 8) * Nt + gc) = v;
                }
            }
        }
    } else {
        // gate quads interleaved: col 4j+{i,f,g,o}; stage 64-row chunks in smem
        float (*sC)[132] = (float (*)[132])smemc;
        const int j0 = col0 >> 2;
        for (int ch = 0; ch < 2; ch++) {
            __syncthreads();
            if (wm == ch) {
#pragma unroll
                for (int mf = 0; mf < 4; mf++) {
                    int rl = mf * 16 + (lane >> 2);
#pragma unroll
                    for (int nf = 0; nf < 4; nf++) {
                        int cl = wn * 32 + nf * 8 + 2 * (lane & 3);
                        float b0 = bias[col0 + cl], b1 = bias[col0 + cl + 1];
                        sC[rl][cl] = acc[mf][nf][0] + b0;
                        sC[rl][cl + 1] = acc[mf][nf][1] + b1;
                        sC[rl + 8][cl] = acc[mf][nf][2] + b0;
                        sC[rl + 8][cl + 1] = acc[mf][nf][3] + b1;
                    }
                }
            }
            __syncthreads();
            for (int q = tid; q < 64 * 32; q += 256) {
                int rl = q >> 5, jl = q & 31;
                int node = row0 + ch * 64 + rl;
                if (node < M) {
                    float4 g4 = *(float4*)&sC[rl][4 * jl];
                    size_t ci = (size_t)node * HH + j0 + jl;
                    float cn = sigm(g4.y) * cstate[ci] + sigm(g4.x) * tanhf(g4.z);
                    cstate[ci] = cn;
                    float hv = sigm(g4.w) * tanhf(cn);
                    if (hout) hout[ci] = hv;
                    split_bf16(hv, houth[ci], houtl[ci]);
                }
            }
        }
    }
}

// warp per node: out = h2 . out_w + out_b
__global__ void out_proj_kernel(const float* __restrict__ h2, const float* __restrict__ w,
                                const float* __restrict__ b, float* __restrict__ out, int n) {
    int gw = (blockIdx.x * blockDim.x + threadIdx.x) >> 5;
    int lane = threadIdx.x & 31;
    if (gw >= n) return;
    float4 hv = ((const float4*)(h2 + (size_t)gw * HH))[lane];
    float4 wv = ((const float4*)w)[lane];
    float s = hv.x * wv.x + hv.y * wv.y + hv.z * wv.z + hv.w * wv.w;
#pragma unroll
    for (int off = 16; off; off >>= 1) s += __shfl_xor_sync(0xFFFFFFFFu, s, off);
    if (lane == 0) out[gw] = s + b[0];
}

__global__ void copy_states_kernel(const float* __restrict__ st, float* __restrict__ out, size_t nh) {
    size_t i = (size_t)blockIdx.x * blockDim.x + threadIdx.x;
    size_t total = 4 * nh;
    for (; i < total; i += (size_t)gridDim.x * blockDim.x) out[i] = st[i];
}

// ---------------- host launch ----------------
static inline int cdiv(int a, int b) { return (a + b - 1) / b; }
#define SYM(var, sym) cudaGetSymbolAddress((void**)&var, sym)

extern "C" void kernel_launch(void* const* d_in, const int* in_sizes, int n_in,
                              void* d_out, int out_size) {
    const float* x    = (const float*)d_in[0];
    const void*  ei   = d_in[1];
    const float* gw1  = (const float*)d_in[2];
    const float* gb1  = (const float*)d_in[3];
    const float* gw2  = (const float*)d_in[4];
    const float* gb2  = (const float*)d_in[5];
    const float* wih1 = (const float*)d_in[6];
    const float* whh1 = (const float*)d_in[7];
    const float* bih1 = (const float*)d_in[8];
    const float* bhh1 = (const float*)d_in[9];
    const float* wih2 = (const float*)d_in[10];
    const float* whh2 = (const float*)d_in[11];
    const float* bih2 = (const float*)d_in[12];
    const float* bhh2 = (const float*)d_in[13];
    const float* outw = (const float*)d_in[14];
    const float* outb = (const float*)d_in[15];

    const int N = in_sizes[0] / (TT * FIN);
    const int E = in_sizes[1] / (2 * TT);
    float* out = (float*)d_out;

    __nv_bfloat16 *xh, *xl, *fh, *fl, *b2h, *b2l;
    __nv_bfloat16 *h1h_a, *h1l_a, *h1h_b, *h1l_b, *h2h_a, *h2l_a, *h2h_b, *h2l_b;
    __nv_bfloat16 *B1h, *B1l, *B2h, *B2l, *GW1h, *GW1l, *GW2h, *GW2l;
    float *nis, *hlin, *agg, *hbuf, *state, *bias1, *bias2;
    SYM(xh, g_xh); SYM(xl, g_xl); SYM(fh, g_fh); SYM(fl, g_fl);
    SYM(b2h, g_b2h); SYM(b2l, g_b2l);
    SYM(h1h_a, g_h1h_a); SYM(h1l_a, g_h1l_a); SYM(h1h_b, g_h1h_b); SYM(h1l_b, g_h1l_b);
    SYM(h2h_a, g_h2h_a); SYM(h2l_a, g_h2l_a); SYM(h2h_b, g_h2h_b); SYM(h2l_b, g_h2l_b);
    SYM(B1h, g_B1h); SYM(B1l, g_B1l); SYM(B2h, g_B2h); SYM(B2l, g_B2l);
    SYM(GW1h, g_GW1h); SYM(GW1l, g_GW1l); SYM(GW2h, g_GW2h); SYM(GW2l, g_GW2l);
    SYM(nis, g_nis); SYM(hlin, g_hlin); SYM(agg, g_agg);
    SYM(hbuf, g_hbuf); SYM(state, g_state); SYM(bias1, g_bias1); SYM(bias2, g_bias2);

    const size_t NH = (size_t)N * HH;
    const long long TN = (long long)TT * N;
    const long long TNH = TN * HH;

    const int mbA = (int)((TN + BM - 1) / BM);  // 3125
    const int mbL = cdiv(N, BM);                // 391

    // launch order keeps GCN L1 GEMM at #5 for ncu comparability across rounds
    detect_idx_kernel<<<1, 1>>>(ei);                                            // 1
    prep_weights_kernel<<<cdiv(512 * 256, 256), 256>>>(gw1, gw2, wih1, whh1,    // 2
                                                       bih1, bhh1, wih2, whh2, bih2, bhh2);
    split_x_kernel<<<2048, 256>>>(x, (size_t)TN * FIN);                         // 3
    cudaMemsetAsync(nis, 0, TN * sizeof(float));                                // 4

    // -------- GCN layer 1 GEMM (batched over all t; streaming, L2-safe) ----- // 5
    mma_gemm_kernel<false><<<dim3(1, mbA), 256>>>(
        (int)TN, HH, 128, xh, xl, nullptr, nullptr, GW1h, GW1l, gb1,
        hlin, nullptr, nullptr, nullptr, nullptr);

    deg_all_kernel<<<(unsigned)(((long long)TT * E + 255) / 256), 256>>>(ei, E, N, nis);
    nis_all_kernel<<<(unsigned)((TN + 255) / 256), 256>>>(nis, TN);

    // -------- GCN layer 1 scatter: PER-T passes (51MB working set, L2-resident)
    cudaMemsetAsync(agg, 0, TNH * sizeof(float));
    for (int t = 0; t < TT; t++) {
        size_t srcOff = (size_t)t * 2 * E;
        const float* nis_t = nis + (size_t)t * N;
        const float* hlin_t = hlin + (size_t)t * NH;
        float* agg_t = agg + (size_t)t * NH;
        edge_msg_kernel<<<cdiv(E * 32, 256), 256>>>(ei, srcOff, srcOff + E, E, nis_t, hlin_t, agg_t);
        gcn_combine_kernel<<<cdiv(N * HH, 256), 256>>>(agg_t, hlin_t, nis_t,
                                                       b2h + (size_t)t * NH, b2l + (size_t)t * NH, N);
    }

    // -------- GCN layer 2 --------
    mma_gemm_kernel<false><<<dim3(1, mbA), 256>>>(
        (int)TN, HH, 128, b2h, b2l, nullptr, nullptr, GW2h, GW2l, gb2,
        hlin, nullptr, nullptr, nullptr, nullptr);
    cudaMemsetAsync(agg, 0, TNH * sizeof(float));
    for (int t = 0; t < TT; t++) {
        size_t srcOff = (size_t)t * 2 * E;
        const float* nis_t = nis + (size_t)t * N;
        const float* hlin_t = hlin + (size_t)t * NH;
        float* agg_t = agg + (size_t)t * NH;
        edge_msg_kernel<<<cdiv(E * 32, 256), 256>>>(ei, srcOff, srcOff + E, E, nis_t, hlin_t, agg_t);
        gcn_combine_kernel<<<cdiv(N * HH, 256), 256>>>(agg_t, hlin_t, nis_t,
                                                       fh + (size_t)t * NH, fl + (size_t)t * NH, N);
    }

    // -------- LSTM over time (fused gates+cell GEMM, ping-pong h planes) -----
    cudaMemsetAsync(state, 0, 4 * NH * sizeof(float));
    cudaMemsetAsync(h1h_a, 0, NH * sizeof(__nv_bfloat16));
    cudaMemsetAsync(h1l_a, 0, NH * sizeof(__nv_bfloat16));
    cudaMemsetAsync(h2h_a, 0, NH * sizeof(__nv_bfloat16));
    cudaMemsetAsync(h2l_a, 0, NH * sizeof(__nv_bfloat16));

    float* h1a = state;               // final h1 (t=7 odd writes A bufs)
    float* c1  = state + NH;
    float* h2a = state + 2 * NH;
    float* c2  = state + 3 * NH;
    float* h2b = hbuf;                // fp32 h2 for out_proj on even t

    for (int t = 0; t < TT; t++) {
        const int odd = t & 1;
        const __nv_bfloat16* h1ih = odd ? h1h_b : h1h_a;
        const __nv_bfloat16* h1il = odd ? h1l_b : h1l_a;
        __nv_bfloat16* h1oh = odd ? h1h_a : h1h_b;
        __nv_bfloat16* h1ol = odd ? h1l_a : h1l_b;
        const __nv_bfloat16* h2ih = odd ? h2h_b : h2h_a;
        const __nv_bfloat16* h2il = odd ? h2l_b : h2l_a;
        __nv_bfloat16* h2oh = odd ? h2h_a : h2h_b;
        __nv_bfloat16* h2ol = odd ? h2l_a : h2l_b;
        float* h1_out = (t == TT - 1) ? h1a : nullptr;   // fp32 h1 only needed at the end
        float* h2_out = odd ? h2a : h2b;                 // fp32 h2 for out_proj each t

        // layer 1: K=256 [feats_t ; h1_{t-1}]
        mma_gemm_kernel<true><<<dim3(4, mbL), 256>>>(
            N, G4, 256, fh + (size_t)t * NH, fl + (size_t)t * NH, h1ih, h1il,
            B1h, B1l, bias1, nullptr, c1, h1_out, h1oh, h1ol);
        // layer 2: K=256 [h1_t ; h2_{t-1}]
        mma_gemm_kernel<true><<<dim3(4, mbL), 256>>>(
            N, G4, 256, h1oh, h1ol, h2ih, h2il,
            B2h, B2l, bias2, nullptr, c2, h2_out, h2oh, h2ol);
        out_proj_kernel<<<cdiv(N * 32, 256), 256>>>(h2_out, outw, outb, out + (size_t)t * N, N);
    }

    // -------- tail: h1, c1, h2, c2 (t=7 odd -> finals in buf A = state) ------
    copy_states_kernel<<<1024, 256>>>(state, out + (size_t)TT * N, NH);
}

// round 9
// speedup vs baseline: 1.3803x; 1.2182x over previous
#include <cuda_runtime.h>
#include <cuda_bf16.h>
#include <math.h>
#include <stdint.h>

#define TT 8
#define FIN 128
#define HH 128
#define NMAX 50048
#define EMAX 800000
#define G4 (4*HH)

// ---------------- device scratch (allocation-free rule: __device__ globals) ----
static __device__ __nv_bfloat16 g_xh[(size_t)TT * NMAX * HH];
static __device__ __nv_bfloat16 g_xl[(size_t)TT * NMAX * HH];
static __device__ __nv_bfloat16 g_fh[(size_t)TT * NMAX * HH];   // feats hi
static __device__ __nv_bfloat16 g_fl[(size_t)TT * NMAX * HH];   // feats lo
static __device__ __nv_bfloat16 g_b2h[(size_t)TT * NMAX * HH];  // gcn layer1 out hi
static __device__ __nv_bfloat16 g_b2l[(size_t)TT * NMAX * HH];
static __device__ float g_nis[(size_t)TT * NMAX];               // deg then deg^{-1/2}
static __device__ float g_hlin[(size_t)TT * NMAX * HH];         // batched x@W+b
static __device__ int   g_offs[(size_t)TT * (NMAX + 1)];        // CSR row offsets
static __device__ int   g_cursor[(size_t)TT * NMAX];            // fill cursors
static __device__ int   g_csr[(size_t)TT * EMAX];               // src ids grouped by dst
static __device__ float g_hbuf[(size_t)2 * NMAX * HH];          // fp32 h2 B buf + spare
static __device__ float g_state[(size_t)4 * NMAX * HH];         // h1a,c1,h2a,c2
static __device__ __nv_bfloat16 g_h1h_a[(size_t)NMAX * HH];
static __device__ __nv_bfloat16 g_h1l_a[(size_t)NMAX * HH];
static __device__ __nv_bfloat16 g_h1h_b[(size_t)NMAX * HH];
static __device__ __nv_bfloat16 g_h1l_b[(size_t)NMAX * HH];
static __device__ __nv_bfloat16 g_h2h_a[(size_t)NMAX * HH];
static __device__ __nv_bfloat16 g_h2l_a[(size_t)NMAX * HH];
static __device__ __nv_bfloat16 g_h2h_b[(size_t)NMAX * HH];
static __device__ __nv_bfloat16 g_h2l_b[(size_t)NMAX * HH];
// LSTM weights, gate-interleaved cols [n'=4j+g][k], K-major, K=256 = [Wih ; Whh]
static __device__ __nv_bfloat16 g_B1h[512 * 256];
static __device__ __nv_bfloat16 g_B1l[512 * 256];
static __device__ __nv_bfloat16 g_B2h[512 * 256];
static __device__ __nv_bfloat16 g_B2l[512 * 256];
static __device__ __nv_bfloat16 g_GW1h[128 * 128];              // gcn W^T [n][k]
static __device__ __nv_bfloat16 g_GW1l[128 * 128];
static __device__ __nv_bfloat16 g_GW2h[128 * 128];
static __device__ __nv_bfloat16 g_GW2l[128 * 128];
static __device__ float g_bias1[G4];
static __device__ float g_bias2[G4];
static __device__ int   g_idx64;

// ---------------- helpers ----------------
__device__ __forceinline__ int load_idx(const void* p, size_t off) {
    return g_idx64 ? (int)((const long long*)p)[off] : ((const int*)p)[off];
}
__device__ __forceinline__ float sigm(float x) { return 1.0f / (1.0f + expf(-x)); }

__device__ __forceinline__ void split_bf16(float v, __nv_bfloat16& h, __nv_bfloat16& l) {
    h = __float2bfloat16(v);
    l = __float2bfloat16(v - __bfloat162float(h));
}

__device__ __forceinline__ void cpasync16(uint32_t dst, const void* src, int sz) {
    asm volatile("cp.async.cg.shared.global [%0], [%1], 16, %2;\n" :: "r"(dst), "l"(src), "r"(sz));
}
__device__ __forceinline__ void cp_commit() { asm volatile("cp.async.commit_group;\n"); }
__device__ __forceinline__ void cp_wait1() { asm volatile("cp.async.wait_group 1;\n"); }

__device__ __forceinline__ uint32_t swz(uint32_t o) { return o ^ ((o >> 3) & 0x10); }

__device__ __forceinline__ void ldsm4(uint32_t* r, uint32_t addr) {
    asm volatile("ldmatrix.sync.aligned.m8n8.x4.shared.b16 {%0,%1,%2,%3}, [%4];"
                 : "=r"(r[0]), "=r"(r[1]), "=r"(r[2]), "=r"(r[3]) : "r"(addr));
}

__device__ __forceinline__ void mma_bf16(float* d, const uint32_t* a, const uint32_t* b) {
    asm volatile(
        "mma.sync.aligned.m16n8k16.row.col.f32.bf16.bf16.f32 "
        "{%0,%1,%2,%3}, {%4,%5,%6,%7}, {%8,%9}, {%0,%1,%2,%3};\n"
        : "+f"(d[0]), "+f"(d[1]), "+f"(d[2]), "+f"(d[3])
        : "r"(a[0]), "r"(a[1]), "r"(a[2]), "r"(a[3]), "r"(b[0]), "r"(b[1]));
}

// ---------------- prep kernels ----------------
__global__ void detect_idx_kernel(const void* ei) {
    const int* p = (const int*)ei;
    int s = 0;
    for (int i = 1; i < 257; i += 2) s |= p[i];
    g_idx64 = (s == 0) ? 1 : 0;
}

__global__ void split_x_kernel(const float* __restrict__ x, size_t total) {
    for (size_t i = (size_t)blockIdx.x * blockDim.x + threadIdx.x; i < total;
         i += (size_t)gridDim.x * blockDim.x) {
        split_bf16(x[i], g_xh[i], g_xl[i]);
    }
}

__global__ void prep_weights_kernel(const float* __restrict__ gw1, const float* __restrict__ gw2,
                                    const float* __restrict__ wih1, const float* __restrict__ whh1,
                                    const float* __restrict__ bih1, const float* __restrict__ bhh1,
                                    const float* __restrict__ wih2, const float* __restrict__ whh2,
                                    const float* __restrict__ bih2, const float* __restrict__ bhh2) {
    int idx = blockIdx.x * blockDim.x + threadIdx.x;
    if (idx < 512 * 256) {
        int n = idx >> 8;       // gate-interleaved col 4j+g
        int k = idx & 255;
        int j = n >> 2, g = n & 3;
        int orow = g * 128 + j;
        float v1, v2;
        if (k < 128) { v1 = wih1[orow * 128 + k];         v2 = wih2[orow * 128 + k]; }
        else         { v1 = whh1[orow * 128 + (k - 128)]; v2 = whh2[orow * 128 + (k - 128)]; }
        split_bf16(v1, g_B1h[idx], g_B1l[idx]);
        split_bf16(v2, g_B2h[idx], g_B2l[idx]);
    }
    if (idx < 128 * 128) {
        int n = idx >> 7, k = idx & 127;
        split_bf16(gw1[k * 128 + n], g_GW1h[idx], g_GW1l[idx]);
        split_bf16(gw2[k * 128 + n], g_GW2h[idx], g_GW2l[idx]);
    }
    if (idx < 512) {
        int j = idx >> 2, g = idx & 3;
        int orow = g * 128 + j;
        g_bias1[idx] = bih1[orow] + bhh1[orow];
        g_bias2[idx] = bih2[orow] + bhh2[orow];
    }
}

// ---------------- GCN: degree, CSR build, gather ----------------
__global__ void deg_all_kernel(const void* __restrict__ ei, int E, int N, float* __restrict__ deg) {
    long long i = (long long)blockIdx.x * blockDim.x + threadIdx.x;
    if (i >= (long long)TT * E) return;
    int t = (int)(i / E);
    int e = (int)(i - (long long)t * E);
    int d = load_idx(ei, (size_t)t * 2 * E + E + e);
    atomicAdd(&deg[(size_t)t * N + d], 1.0f);
}

// one block per t: exclusive scan of integer degree counts -> CSR offsets
__global__ void scan_offsets_kernel(const float* __restrict__ deg, int* __restrict__ offs, int N) {
    __shared__ int sm[1024];
    __shared__ int sbase;
    const int t = blockIdx.x;
    if (threadIdx.x == 0) sbase = 0;
    __syncthreads();
    const float* dt = deg + (size_t)t * N;
    int* ot = offs + (size_t)t * (N + 1);
    for (int base = 0; base < N; base += 1024) {
        int i = base + threadIdx.x;
        int v = (i < N) ? (int)dt[i] : 0;
        sm[threadIdx.x] = v;
        __syncthreads();
        for (int off = 1; off < 1024; off <<= 1) {
            int x = (threadIdx.x >= off) ? sm[threadIdx.x - off] : 0;
            __syncthreads();
            sm[threadIdx.x] += x;
            __syncthreads();
        }
        int incl = sm[threadIdx.x];
        if (i < N) ot[i] = sbase + incl - v;
        __syncthreads();
        if (threadIdx.x == 1023) sbase += sm[1023];
        __syncthreads();
    }
    if (threadIdx.x == 0) ot[N] = sbase;
}

__global__ void csr_fill_kernel(const void* __restrict__ ei, int E, int N,
                                const int* __restrict__ offs, int* __restrict__ cursor,
                                int* __restrict__ csr) {
    long long i = (long long)blockIdx.x * blockDim.x + threadIdx.x;
    if (i >= (long long)TT * E) return;
    int t = (int)(i / E);
    int e = (int)(i - (long long)t * E);
    int s = load_idx(ei, (size_t)t * 2 * E + e);
    int d = load_idx(ei, (size_t)t * 2 * E + E + e);
    int pos = atomicAdd(&cursor[(size_t)t * N + d], 1);
    csr[(size_t)t * E + offs[(size_t)t * (N + 1) + d] + pos] = s;
}

__global__ void nis_all_kernel(float* __restrict__ nis, long long total) {
    long long i = (long long)blockIdx.x * blockDim.x + threadIdx.x;
    if (i < total) nis[i] = rsqrtf(nis[i] + 1.0f);
}

// warp per dst node: gather CSR src rows, accumulate in regs, fuse combine+relu+split.
// out = relu(nd*(sum_s nis[s]*h[s] + nd*h[d]))
__global__ void gather_combine_kernel(const int* __restrict__ csr_t, const int* __restrict__ offs_t,
                                      const float* __restrict__ nis_t, const float* __restrict__ hlin_t,
                                      __nv_bfloat16* __restrict__ oh, __nv_bfloat16* __restrict__ ol,
                                      int N) {
    int gw = (blockIdx.x * blockDim.x + threadIdx.x) >> 5;
    int lane = threadIdx.x & 31;
    if (gw >= N) return;
    int beg = offs_t[gw], end = offs_t[gw + 1];
    float4 acc = make_float4(0.f, 0.f, 0.f, 0.f);
#pragma unroll 2
    for (int p = beg; p < end; p++) {
        int s = csr_t[p];
        float ns = nis_t[s];
        float4 v = ((const float4*)(hlin_t + (size_t)s * HH))[lane];
        acc.x += v.x * ns; acc.y += v.y * ns; acc.z += v.z * ns; acc.w += v.w * ns;
    }
    float nd = nis_t[gw];
    float4 self = ((const float4*)(hlin_t + (size_t)gw * HH))[lane];
    float4 r;
    r.x = fmaxf(nd * (acc.x + nd * self.x), 0.0f);
    r.y = fmaxf(nd * (acc.y + nd * self.y), 0.0f);
    r.z = fmaxf(nd * (acc.z + nd * self.z), 0.0f);
    r.w = fmaxf(nd * (acc.w + nd * self.w), 0.0f);
    __nv_bfloat16 h0, l0, h1, l1, h2, l2, h3, l3;
    split_bf16(r.x, h0, l0); split_bf16(r.y, h1, l1);
    split_bf16(r.z, h2, l2); split_bf16(r.w, h3, l3);
    __nv_bfloat162* dh = (__nv_bfloat162*)(oh + (size_t)gw * HH + lane * 4);
    __nv_bfloat162* dl = (__nv_bfloat162*)(ol + (size_t)gw * HH + lane * 4);
    dh[0] = __nv_bfloat162(h0, h1); dh[1] = __nv_bfloat162(h2, h3);
    dl[0] = __nv_bfloat162(l0, l1); dl[1] = __nv_bfloat162(l2, l3);
}

// ---------------- emulated-fp32 GEMM via bf16x2 (3-term) tensor mma ----------
#define BM 128
#define BN 128
#define BKK 16
#define STAGEB 16384   // Ah(4K) + Al(4K) + Bh(4K) + Bl(4K) per stage

template<bool LSTM>
__global__ __launch_bounds__(256) void mma_gemm_kernel(
    int M, int Nt, int K,
    const __nv_bfloat16* __restrict__ A1h, const __nv_bfloat16* __restrict__ A1l,
    const __nv_bfloat16* __restrict__ A2h, const __nv_bfloat16* __restrict__ A2l,
    const __nv_bfloat16* __restrict__ Bth, const __nv_bfloat16* __restrict__ Btl,
    const float* __restrict__ bias,
    float* __restrict__ Cout, float* __restrict__ cstate,
    float* __restrict__ hout, __nv_bfloat16* __restrict__ houth, __nv_bfloat16* __restrict__ houtl) {

    __shared__ __align__(16) char smemc[3 * STAGEB];   // 48KB
    const uint32_t smemBase = (uint32_t)__cvta_generic_to_shared(smemc);

    const int tid = threadIdx.x;
    const int lane = tid & 31;
    const int wid = tid >> 5;
    const int wm = wid >> 2;          // 0..1
    const int wn = wid & 3;           // 0..3
    const int row0 = blockIdx.y * BM;
    const int col0 = blockIdx.x * BN;

    float acc[4][4][4];
#pragma unroll
    for (int i = 0; i < 4; i++)
#pragma unroll
        for (int j = 0; j < 4; j++)
#pragma unroll
            for (int v = 0; v < 4; v++) acc[i][j][v] = 0.0f;

    const int KT = K / BKK;

    const int lrow = tid >> 1;        // 0..127
    const int lh = tid & 1;
    const uint32_t dOff = swz((uint32_t)(lrow * 32 + lh * 16));

    auto load_tile = [&](int kt, int buf) {
        const int k0 = kt * BKK;
        const __nv_bfloat16 *Aph, *Apl;
        int kk;
        if (k0 < 128) { Aph = A1h; Apl = A1l; kk = k0; }
        else          { Aph = A2h; Apl = A2l; kk = k0 - 128; }
        const uint32_t base = smemBase + buf * STAGEB;
        const int gr = row0 + lrow;
        const int pa = (gr < M) ? 16 : 0;
        const size_t aoff = (size_t)gr * 128 + kk + lh * 8;
        cpasync16(base + dOff,         Aph + aoff, pa);
        cpasync16(base + 4096 + dOff,  Apl + aoff, pa);
        const size_t boff = (size_t)(col0 + lrow) * K + k0 + lh * 8;
        cpasync16(base + 8192 + dOff,  Bth + boff, 16);
        cpasync16(base + 12288 + dOff, Btl + boff, 16);
    };

    const int a_r = lane & 15;
    const int a_h = lane >> 4;
    const int b_n = (lane & 7) + ((lane >> 4) << 3);
    const int b_h = (lane >> 3) & 1;

    load_tile(0, 0);
    cp_commit();
    if (KT > 1) { load_tile(1, 1); }
    cp_commit();

    int buf = 0;
    for (int kt = 0; kt < KT; kt++) {
        cp_wait1();
        __syncthreads();
        const uint32_t base = smemBase + buf * STAGEB;

        uint32_t ah[4][4], al[4][4], bh[4][2], bl[4][2];
#pragma unroll
        for (int mf = 0; mf < 4; mf++) {
            uint32_t ao = swz((uint32_t)((wm * 64 + mf * 16 + a_r) * 32 + a_h * 16));
            ldsm4(ah[mf], base + ao);
            ldsm4(al[mf], base + 4096 + ao);
        }
#pragma unroll
        for (int nf2 = 0; nf2 < 2; nf2++) {
            uint32_t bo = swz((uint32_t)((wn * 32 + nf2 * 16 + b_n) * 32 + b_h * 16));
            uint32_t t4[4];
            ldsm4(t4, base + 8192 + bo);
            bh[2 * nf2][0] = t4[0]; bh[2 * nf2][1] = t4[1];
            bh[2 * nf2 + 1][0] = t4[2]; bh[2 * nf2 + 1][1] = t4[3];
            ldsm4(t4, base + 12288 + bo);
            bl[2 * nf2][0] = t4[0]; bl[2 * nf2][1] = t4[1];
            bl[2 * nf2 + 1][0] = t4[2]; bl[2 * nf2 + 1][1] = t4[3];
        }
#pragma unroll
        for (int mf = 0; mf < 4; mf++)
#pragma unroll
            for (int nf = 0; nf < 4; nf++) {
                mma_bf16(acc[mf][nf], ah[mf], bh[nf]);
                mma_bf16(acc[mf][nf], ah[mf], bl[nf]);
                mma_bf16(acc[mf][nf], al[mf], bh[nf]);
            }

        if (kt + 2 < KT) {
            int nbuf = buf + 2; if (nbuf >= 3) nbuf -= 3;
            load_tile(kt + 2, nbuf);
        }
        cp_commit();
        if (++buf == 3) buf = 0;
    }
    __syncthreads();

    if (!LSTM) {
#pragma unroll
        for (int mf = 0; mf < 4; mf++) {
            int gr = row0 + wm * 64 + mf * 16 + (lane >> 2);
#pragma unroll
            for (int nf = 0; nf < 4; nf++) {
                int gc = col0 + wn * 32 + nf * 8 + 2 * (lane & 3);
                float b0 = bias[gc], b1 = bias[gc + 1];
                if (gr < M) {
                    float2 v = make_float2(acc[mf][nf][0] + b0, acc[mf][nf][1] + b1);
                    *(float2*)(Cout + (size_t)gr * Nt + gc) = v;
                }
                if (gr + 8 < M) {
                    float2 v = make_float2(acc[mf][nf][2] + b0, acc[mf][nf][3] + b1);
                    *(float2*)(Cout + (size_t)(gr + 8) * Nt + gc) = v;
                }
            }
        }
    } else {
        // gate quads interleaved: col 4j+{i,f,g,o}; stage 64-row chunks in smem
        float (*sC)[132] = (float (*)[132])smemc;
        const int j0 = col0 >> 2;
        for (int ch = 0; ch < 2; ch++) {
            __syncthreads();
            if (wm == ch) {
#pragma unroll
                for (int mf = 0; mf < 4; mf++) {
                    int rl = mf * 16 + (lane >> 2);
#pragma unroll
                    for (int nf = 0; nf < 4; nf++) {
                        int cl = wn * 32 + nf * 8 + 2 * (lane & 3);
                        float b0 = bias[col0 + cl], b1 = bias[col0 + cl + 1];
                        sC[rl][cl] = acc[mf][nf][0] + b0;
                        sC[rl][cl + 1] = acc[mf][nf][1] + b1;
                        sC[rl + 8][cl] = acc[mf][nf][2] + b0;
                        sC[rl + 8][cl + 1] = acc[mf][nf][3] + b1;
                    }
                }
            }
            __syncthreads();
            for (int q = tid; q < 64 * 32; q += 256) {
                int rl = q >> 5, jl = q & 31;
                int node = row0 + ch * 64 + rl;
                if (node < M) {
                    float4 g4 = *(float4*)&sC[rl][4 * jl];
                    size_t ci = (size_t)node * HH + j0 + jl;
                    float cn = sigm(g4.y) * cstate[ci] + sigm(g4.x) * tanhf(g4.z);
                    cstate[ci] = cn;
                    float hv = sigm(g4.w) * tanhf(cn);
                    if (hout) hout[ci] = hv;
                    split_bf16(hv, houth[ci], houtl[ci]);
                }
            }
        }
    }
}

// warp per node: out = h2 . out_w + out_b
__global__ void out_proj_kernel(const float* __restrict__ h2, const float* __restrict__ w,
                                const float* __restrict__ b, float* __restrict__ out, int n) {
    int gw = (blockIdx.x * blockDim.x + threadIdx.x) >> 5;
    int lane = threadIdx.x & 31;
    if (gw >= n) return;
    float4 hv = ((const float4*)(h2 + (size_t)gw * HH))[lane];
    float4 wv = ((const float4*)w)[lane];
    float s = hv.x * wv.x + hv.y * wv.y + hv.z * wv.z + hv.w * wv.w;
#pragma unroll
    for (int off = 16; off; off >>= 1) s += __shfl_xor_sync(0xFFFFFFFFu, s, off);
    if (lane == 0) out[gw] = s + b[0];
}

__global__ void copy_states_kernel(const float* __restrict__ st, float* __restrict__ out, size_t nh) {
    size_t i = (size_t)blockIdx.x * blockDim.x + threadIdx.x;
    size_t total = 4 * nh;
    for (; i < total; i += (size_t)gridDim.x * blockDim.x) out[i] = st[i];
}

// ---------------- host launch ----------------
static inline int cdiv(int a, int b) { return (a + b - 1) / b; }
#define SYM(var, sym) cudaGetSymbolAddress((void**)&var, sym)

extern "C" void kernel_launch(void* const* d_in, const int* in_sizes, int n_in,
                              void* d_out, int out_size) {
    const float* x    = (const float*)d_in[0];
    const void*  ei   = d_in[1];
    const float* gw1  = (const float*)d_in[2];
    const float* gb1  = (const float*)d_in[3];
    const float* gw2  = (const float*)d_in[4];
    const float* gb2  = (const float*)d_in[5];
    const float* wih1 = (const float*)d_in[6];
    const float* whh1 = (const float*)d_in[7];
    const float* bih1 = (const float*)d_in[8];
    const float* bhh1 = (const float*)d_in[9];
    const float* wih2 = (const float*)d_in[10];
    const float* whh2 = (const float*)d_in[11];
    const float* bih2 = (const float*)d_in[12];
    const float* bhh2 = (const float*)d_in[13];
    const float* outw = (const float*)d_in[14];
    const float* outb = (const float*)d_in[15];

    const int N = in_sizes[0] / (TT * FIN);
    const int E = in_sizes[1] / (2 * TT);
    float* out = (float*)d_out;

    __nv_bfloat16 *xh, *xl, *fh, *fl, *b2h, *b2l;
    __nv_bfloat16 *h1h_a, *h1l_a, *h1h_b, *h1l_b, *h2h_a, *h2l_a, *h2h_b, *h2l_b;
    __nv_bfloat16 *B1h, *B1l, *B2h, *B2l, *GW1h, *GW1l, *GW2h, *GW2l;
    float *nis, *hlin, *hbuf, *state, *bias1, *bias2;
    int *offs, *cursor, *csr;
    SYM(xh, g_xh); SYM(xl, g_xl); SYM(fh, g_fh); SYM(fl, g_fl);
    SYM(b2h, g_b2h); SYM(b2l, g_b2l);
    SYM(h1h_a, g_h1h_a); SYM(h1l_a, g_h1l_a); SYM(h1h_b, g_h1h_b); SYM(h1l_b, g_h1l_b);
    SYM(h2h_a, g_h2h_a); SYM(h2l_a, g_h2l_a); SYM(h2h_b, g_h2h_b); SYM(h2l_b, g_h2l_b);
    SYM(B1h, g_B1h); SYM(B1l, g_B1l); SYM(B2h, g_B2h); SYM(B2l, g_B2l);
    SYM(GW1h, g_GW1h); SYM(GW1l, g_GW1l); SYM(GW2h, g_GW2h); SYM(GW2l, g_GW2l);
    SYM(nis, g_nis); SYM(hlin, g_hlin);
    SYM(offs, g_offs); SYM(cursor, g_cursor); SYM(csr, g_csr);
    SYM(hbuf, g_hbuf); SYM(state, g_state); SYM(bias1, g_bias1); SYM(bias2, g_bias2);

    const size_t NH = (size_t)N * HH;
    const long long TN = (long long)TT * N;

    const int mbA = (int)((TN + BM - 1) / BM);  // 3125
    const int mbL = cdiv(N, BM);                // 391

    // launch order keeps GCN L1 GEMM at #5 (ncu sentinel across rounds)
    detect_idx_kernel<<<1, 1>>>(ei);                                            // 1
    prep_weights_kernel<<<cdiv(512 * 256, 256), 256>>>(gw1, gw2, wih1, whh1,    // 2
                                                       bih1, bhh1, wih2, whh2, bih2, bhh2);
    split_x_kernel<<<2048, 256>>>(x, (size_t)TN * FIN);                         // 3
    cudaMemsetAsync(nis, 0, TN * sizeof(float));                                // 4

    // -------- GCN layer 1 GEMM (batched over all t) --------                  // 5
    mma_gemm_kernel<false><<<dim3(1, mbA), 256>>>(
        (int)TN, HH, 128, xh, xl, nullptr, nullptr, GW1h, GW1l, gb1,
        hlin, nullptr, nullptr, nullptr, nullptr);

    // -------- degrees -> CSR offsets -> fill -> nis --------
    deg_all_kernel<<<(unsigned)(((long long)TT * E + 255) / 256), 256>>>(ei, E, N, nis);
    scan_offsets_kernel<<<TT, 1024>>>(nis, offs, N);
    cudaMemsetAsync(cursor, 0, (size_t)TT * N * sizeof(int));
    csr_fill_kernel<<<(unsigned)(((long long)TT * E + 255) / 256), 256>>>(ei, E, N, offs, cursor, csr);
    nis_all_kernel<<<(unsigned)((TN + 255) / 256), 256>>>(nis, TN);

    // -------- GCN layer 1 gather (per-t; fused combine+relu+split) --------
    for (int t = 0; t < TT; t++) {
        gather_combine_kernel<<<cdiv(N * 32, 256), 256>>>(
            csr + (size_t)t * E, offs + (size_t)t * (N + 1),
            nis + (size_t)t * N, hlin + (size_t)t * NH,
            b2h + (size_t)t * NH, b2l + (size_t)t * NH, N);
    }

    // -------- GCN layer 2 --------
    mma_gemm_kernel<false><<<dim3(1, mbA), 256>>>(
        (int)TN, HH, 128, b2h, b2l, nullptr, nullptr, GW2h, GW2l, gb2,
        hlin, nullptr, nullptr, nullptr, nullptr);
    for (int t = 0; t < TT; t++) {
        gather_combine_kernel<<<cdiv(N * 32, 256), 256>>>(
            csr + (size_t)t * E, offs + (size_t)t * (N + 1),
            nis + (size_t)t * N, hlin + (size_t)t * NH,
            fh + (size_t)t * NH, fl + (size_t)t * NH, N);
    }

    // -------- LSTM over time (fused gates+cell GEMM, ping-pong h planes) -----
    cudaMemsetAsync(state, 0, 4 * NH * sizeof(float));
    cudaMemsetAsync(h1h_a, 0, NH * sizeof(__nv_bfloat16));
    cudaMemsetAsync(h1l_a, 0, NH * sizeof(__nv_bfloat16));
    cudaMemsetAsync(h2h_a, 0, NH * sizeof(__nv_bfloat16));
    cudaMemsetAsync(h2l_a, 0, NH * sizeof(__nv_bfloat16));

    float* h1a = state;               // final h1 (t=7 odd writes A bufs)
    float* c1  = state + NH;
    float* h2a = state + 2 * NH;
    float* c2  = state + 3 * NH;
    float* h2b = hbuf;                // fp32 h2 for out_proj on even t

    for (int t = 0; t < TT; t++) {
        const int odd = t & 1;
        const __nv_bfloat16* h1ih = odd ? h1h_b : h1h_a;
        const __nv_bfloat16* h1il = odd ? h1l_b : h1l_a;
        __nv_bfloat16* h1oh = odd ? h1h_a : h1h_b;
        __nv_bfloat16* h1ol = odd ? h1l_a : h1l_b;
        const __nv_bfloat16* h2ih = odd ? h2h_b : h2h_a;
        const __nv_bfloat16* h2il = odd ? h2l_b : h2l_a;
        __nv_bfloat16* h2oh = odd ? h2h_a : h2h_b;
        __nv_bfloat16* h2ol = odd ? h2l_a : h2l_b;
        float* h1_out = (t == TT - 1) ? h1a : nullptr;   // fp32 h1 only needed at the end
        float* h2_out = odd ? h2a : h2b;                 // fp32 h2 for out_proj each t

        // layer 1: K=256 [feats_t ; h1_{t-1}]
        mma_gemm_kernel<true><<<dim3(4, mbL), 256>>>(
            N, G4, 256, fh + (size_t)t * NH, fl + (size_t)t * NH, h1ih, h1il,
            B1h, B1l, bias1, nullptr, c1, h1_out, h1oh, h1ol);
        // layer 2: K=256 [h1_t ; h2_{t-1}]
        mma_gemm_kernel<true><<<dim3(4, mbL), 256>>>(
            N, G4, 256, h1oh, h1ol, h2ih, h2il,
            B2h, B2l, bias2, nullptr, c2, h2_out, h2oh, h2ol);
        out_proj_kernel<<<cdiv(N * 32, 256), 256>>>(h2_out, outw, outb, out + (size_t)t * N, N);
    }

    // -------- tail: h1, c1, h2, c2 (t=7 odd -> finals in buf A = state) ------
    copy_states_kernel<<<1024, 256>>>(state, out + (size_t)TT * N, NH);
}

// round 10
// speedup vs baseline: 1.3988x; 1.0134x over previous
#include <cuda_runtime.h>
#include <cuda_bf16.h>
#include <math.h>
#include <stdint.h>

#define TT 8
#define FIN 128
#define HH 128
#define NMAX 50048
#define EMAX 800000
#define G4 (4*HH)

// ---------------- device scratch (allocation-free rule: __device__ globals) ----
static __device__ __nv_bfloat16 g_xh[(size_t)TT * NMAX * HH];
static __device__ __nv_bfloat16 g_xl[(size_t)TT * NMAX * HH];
static __device__ __nv_bfloat16 g_fh[(size_t)TT * NMAX * HH];   // feats hi
static __device__ __nv_bfloat16 g_fl[(size_t)TT * NMAX * HH];   // feats lo
static __device__ __nv_bfloat16 g_b2h[(size_t)TT * NMAX * HH];  // gcn layer1 out hi
static __device__ __nv_bfloat16 g_b2l[(size_t)TT * NMAX * HH];
static __device__ float g_nis[(size_t)TT * NMAX];               // deg then deg^{-1/2}
static __device__ float g_hlin[(size_t)TT * NMAX * HH];         // batched x@W+b
static __device__ int   g_offs[(size_t)TT * (NMAX + 1)];        // CSR row offsets
static __device__ int   g_cursor[(size_t)TT * NMAX];            // fill cursors
static __device__ int   g_csr[(size_t)TT * EMAX];               // src ids grouped by dst
static __device__ float g_state[(size_t)4 * NMAX * HH];         // h1a,c1,h2a,c2
static __device__ __nv_bfloat16 g_h1h_a[(size_t)NMAX * HH];
static __device__ __nv_bfloat16 g_h1l_a[(size_t)NMAX * HH];
static __device__ __nv_bfloat16 g_h1h_b[(size_t)NMAX * HH];
static __device__ __nv_bfloat16 g_h1l_b[(size_t)NMAX * HH];
static __device__ __nv_bfloat16 g_h2h_a[(size_t)NMAX * HH];
static __device__ __nv_bfloat16 g_h2l_a[(size_t)NMAX * HH];
static __device__ __nv_bfloat16 g_h2h_b[(size_t)NMAX * HH];
static __device__ __nv_bfloat16 g_h2l_b[(size_t)NMAX * HH];
// LSTM weights, gate-interleaved cols [n'=4j+g][k], K-major, K=256 = [Wih ; Whh]
static __device__ __nv_bfloat16 g_B1h[512 * 256];
static __device__ __nv_bfloat16 g_B1l[512 * 256];
static __device__ __nv_bfloat16 g_B2h[512 * 256];
static __device__ __nv_bfloat16 g_B2l[512 * 256];
static __device__ __nv_bfloat16 g_GW1h[128 * 128];              // gcn W^T [n][k]
static __device__ __nv_bfloat16 g_GW1l[128 * 128];
static __device__ __nv_bfloat16 g_GW2h[128 * 128];
static __device__ __nv_bfloat16 g_GW2l[128 * 128];
static __device__ float g_bias1[G4];
static __device__ float g_bias2[G4];
static __device__ int   g_idx64;

// ---------------- helpers ----------------
__device__ __forceinline__ int load_idx(const void* p, size_t off) {
    return g_idx64 ? (int)((const long long*)p)[off] : ((const int*)p)[off];
}
__device__ __forceinline__ float sigm(float x) { return 1.0f / (1.0f + expf(-x)); }

__device__ __forceinline__ void split_bf16(float v, __nv_bfloat16& h, __nv_bfloat16& l) {
    h = __float2bfloat16(v);
    l = __float2bfloat16(v - __bfloat162float(h));
}

__device__ __forceinline__ void cpasync16(uint32_t dst, const void* src, int sz) {
    asm volatile("cp.async.cg.shared.global [%0], [%1], 16, %2;\n" :: "r"(dst), "l"(src), "r"(sz));
}
__device__ __forceinline__ void cp_commit() { asm volatile("cp.async.commit_group;\n"); }
__device__ __forceinline__ void cp_wait1() { asm volatile("cp.async.wait_group 1;\n"); }

__device__ __forceinline__ uint32_t swz(uint32_t o) { return o ^ ((o >> 3) & 0x10); }

__device__ __forceinline__ void ldsm4(uint32_t* r, uint32_t addr) {
    asm volatile("ldmatrix.sync.aligned.m8n8.x4.shared.b16 {%0,%1,%2,%3}, [%4];"
                 : "=r"(r[0]), "=r"(r[1]), "=r"(r[2]), "=r"(r[3]) : "r"(addr));
}

__device__ __forceinline__ void mma_bf16(float* d, const uint32_t* a, const uint32_t* b) {
    asm volatile(
        "mma.sync.aligned.m16n8k16.row.col.f32.bf16.bf16.f32 "
        "{%0,%1,%2,%3}, {%4,%5,%6,%7}, {%8,%9}, {%0,%1,%2,%3};\n"
        : "+f"(d[0]), "+f"(d[1]), "+f"(d[2]), "+f"(d[3])
        : "r"(a[0]), "r"(a[1]), "r"(a[2]), "r"(a[3]), "r"(b[0]), "r"(b[1]));
}

// ---------------- prep kernels ----------------
__global__ void detect_idx_kernel(const void* ei) {
    const int* p = (const int*)ei;
    int s = 0;
    for (int i = 1; i < 257; i += 2) s |= p[i];
    g_idx64 = (s == 0) ? 1 : 0;
}

__global__ void split_x_kernel(const float* __restrict__ x, size_t total) {
    for (size_t i = (size_t)blockIdx.x * blockDim.x + threadIdx.x; i < total;
         i += (size_t)gridDim.x * blockDim.x) {
        split_bf16(x[i], g_xh[i], g_xl[i]);
    }
}

__global__ void prep_weights_kernel(const float* __restrict__ gw1, const float* __restrict__ gw2,
                                    const float* __restrict__ wih1, const float* __restrict__ whh1,
                                    const float* __restrict__ bih1, const float* __restrict__ bhh1,
                                    const float* __restrict__ wih2, const float* __restrict__ whh2,
                                    const float* __restrict__ bih2, const float* __restrict__ bhh2) {
    int idx = blockIdx.x * blockDim.x + threadIdx.x;
    if (idx < 512 * 256) {
        int n = idx >> 8;       // gate-interleaved col 4j+g
        int k = idx & 255;
        int j = n >> 2, g = n & 3;
        int orow = g * 128 + j;
        float v1, v2;
        if (k < 128) { v1 = wih1[orow * 128 + k];         v2 = wih2[orow * 128 + k]; }
        else         { v1 = whh1[orow * 128 + (k - 128)]; v2 = whh2[orow * 128 + (k - 128)]; }
        split_bf16(v1, g_B1h[idx], g_B1l[idx]);
        split_bf16(v2, g_B2h[idx], g_B2l[idx]);
    }
    if (idx < 128 * 128) {
        int n = idx >> 7, k = idx & 127;
        split_bf16(gw1[k * 128 + n], g_GW1h[idx], g_GW1l[idx]);
        split_bf16(gw2[k * 128 + n], g_GW2h[idx], g_GW2l[idx]);
    }
    if (idx < 512) {
        int j = idx >> 2, g = idx & 3;
        int orow = g * 128 + j;
        g_bias1[idx] = bih1[orow] + bhh1[orow];
        g_bias2[idx] = bih2[orow] + bhh2[orow];
    }
}

// ---------------- GCN: degree, CSR build, gather ----------------
__global__ void deg_all_kernel(const void* __restrict__ ei, int E, int N, float* __restrict__ deg) {
    long long i = (long long)blockIdx.x * blockDim.x + threadIdx.x;
    if (i >= (long long)TT * E) return;
    int t = (int)(i / E);
    int e = (int)(i - (long long)t * E);
    int d = load_idx(ei, (size_t)t * 2 * E + E + e);
    atomicAdd(&deg[(size_t)t * N + d], 1.0f);
}

// one block per t: exclusive scan of integer degree counts -> CSR offsets
__global__ void scan_offsets_kernel(const float* __restrict__ deg, int* __restrict__ offs, int N) {
    __shared__ int sm[1024];
    __shared__ int sbase;
    const int t = blockIdx.x;
    if (threadIdx.x == 0) sbase = 0;
    __syncthreads();
    const float* dt = deg + (size_t)t * N;
    int* ot = offs + (size_t)t * (N + 1);
    for (int base = 0; base < N; base += 1024) {
        int i = base + threadIdx.x;
        int v = (i < N) ? (int)dt[i] : 0;
        sm[threadIdx.x] = v;
        __syncthreads();
        for (int off = 1; off < 1024; off <<= 1) {
            int x = (threadIdx.x >= off) ? sm[threadIdx.x - off] : 0;
            __syncthreads();
            sm[threadIdx.x] += x;
            __syncthreads();
        }
        int incl = sm[threadIdx.x];
        if (i < N) ot[i] = sbase + incl - v;
        __syncthreads();
        if (threadIdx.x == 1023) sbase += sm[1023];
        __syncthreads();
    }
    if (threadIdx.x == 0) ot[N] = sbase;
}

__global__ void csr_fill_kernel(const void* __restrict__ ei, int E, int N,
                                const int* __restrict__ offs, int* __restrict__ cursor,
                                int* __restrict__ csr) {
    long long i = (long long)blockIdx.x * blockDim.x + threadIdx.x;
    if (i >= (long long)TT * E) return;
    int t = (int)(i / E);
    int e = (int)(i - (long long)t * E);
    int s = load_idx(ei, (size_t)t * 2 * E + e);
    int d = load_idx(ei, (size_t)t * 2 * E + E + e);
    int pos = atomicAdd(&cursor[(size_t)t * N + d], 1);
    csr[(size_t)t * E + offs[(size_t)t * (N + 1) + d] + pos] = s;
}

__global__ void nis_all_kernel(float* __restrict__ nis, long long total) {
    long long i = (long long)blockIdx.x * blockDim.x + threadIdx.x;
    if (i < total) nis[i] = rsqrtf(nis[i] + 1.0f);
}

// warp per dst node: gather CSR src rows, accumulate in regs, fuse combine+relu+split.
// out = relu(nd*(sum_s nis[s]*h[s] + nd*h[d]))
__global__ void gather_combine_kernel(const int* __restrict__ csr_t, const int* __restrict__ offs_t,
                                      const float* __restrict__ nis_t, const float* __restrict__ hlin_t,
                                      __nv_bfloat16* __restrict__ oh, __nv_bfloat16* __restrict__ ol,
                                      int N) {
    int gw = (blockIdx.x * blockDim.x + threadIdx.x) >> 5;
    int lane = threadIdx.x & 31;
    if (gw >= N) return;
    int beg = offs_t[gw], end = offs_t[gw + 1];
    float4 acc = make_float4(0.f, 0.f, 0.f, 0.f);
#pragma unroll 2
    for (int p = beg; p < end; p++) {
        int s = csr_t[p];
        float ns = nis_t[s];
        float4 v = ((const float4*)(hlin_t + (size_t)s * HH))[lane];
        acc.x += v.x * ns; acc.y += v.y * ns; acc.z += v.z * ns; acc.w += v.w * ns;
    }
    float nd = nis_t[gw];
    float4 self = ((const float4*)(hlin_t + (size_t)gw * HH))[lane];
    float4 r;
    r.x = fmaxf(nd * (acc.x + nd * self.x), 0.0f);
    r.y = fmaxf(nd * (acc.y + nd * self.y), 0.0f);
    r.z = fmaxf(nd * (acc.z + nd * self.z), 0.0f);
    r.w = fmaxf(nd * (acc.w + nd * self.w), 0.0f);
    __nv_bfloat16 h0, l0, h1, l1, h2, l2, h3, l3;
    split_bf16(r.x, h0, l0); split_bf16(r.y, h1, l1);
    split_bf16(r.z, h2, l2); split_bf16(r.w, h3, l3);
    __nv_bfloat162* dh = (__nv_bfloat162*)(oh + (size_t)gw * HH + lane * 4);
    __nv_bfloat162* dl = (__nv_bfloat162*)(ol + (size_t)gw * HH + lane * 4);
    dh[0] = __nv_bfloat162(h0, h1); dh[1] = __nv_bfloat162(h2, h3);
    dl[0] = __nv_bfloat162(l0, l1); dl[1] = __nv_bfloat162(l2, l3);
}

// ---------------- emulated-fp32 GEMM via bf16x2 (3-term) tensor mma ----------
// Term-major mma ordering: 16 independent accumulators between reuses ->
// no back-to-back RAW on the tensor pipe (asm volatile pins source order).
#define BM 128
#define BN 128
#define BKK 16
#define STAGEB 16384   // Ah(4K) + Al(4K) + Bh(4K) + Bl(4K) per stage

template<bool LSTM>
__global__ __launch_bounds__(256) void mma_gemm_kernel(
    int M, int Nt, int K,
    const __nv_bfloat16* __restrict__ A1h, const __nv_bfloat16* __restrict__ A1l,
    const __nv_bfloat16* __restrict__ A2h, const __nv_bfloat16* __restrict__ A2l,
    const __nv_bfloat16* __restrict__ Bth, const __nv_bfloat16* __restrict__ Btl,
    const float* __restrict__ bias,
    float* __restrict__ Cout, float* __restrict__ cstate,
    float* __restrict__ hout, __nv_bfloat16* __restrict__ houth, __nv_bfloat16* __restrict__ houtl) {

    __shared__ __align__(16) char smemc[3 * STAGEB];   // 48KB
    const uint32_t smemBase = (uint32_t)__cvta_generic_to_shared(smemc);

    const int tid = threadIdx.x;
    const int lane = tid & 31;
    const int wid = tid >> 5;
    const int wm = wid >> 2;          // 0..1
    const int wn = wid & 3;           // 0..3
    const int row0 = blockIdx.y * BM;
    const int col0 = blockIdx.x * BN;

    float acc[4][4][4];
#pragma unroll
    for (int i = 0; i < 4; i++)
#pragma unroll
        for (int j = 0; j < 4; j++)
#pragma unroll
            for (int v = 0; v < 4; v++) acc[i][j][v] = 0.0f;

    const int KT = K / BKK;

    const int lrow = tid >> 1;        // 0..127
    const int lh = tid & 1;
    const uint32_t dOff = swz((uint32_t)(lrow * 32 + lh * 16));

    auto load_tile = [&](int kt, int buf) {
        const int k0 = kt * BKK;
        const __nv_bfloat16 *Aph, *Apl;
        int kk;
        if (k0 < 128) { Aph = A1h; Apl = A1l; kk = k0; }
        else          { Aph = A2h; Apl = A2l; kk = k0 - 128; }
        const uint32_t base = smemBase + buf * STAGEB;
        const int gr = row0 + lrow;
        const int pa = (gr < M) ? 16 : 0;
        const size_t aoff = (size_t)gr * 128 + kk + lh * 8;
        cpasync16(base + dOff,         Aph + aoff, pa);
        cpasync16(base + 4096 + dOff,  Apl + aoff, pa);
        const size_t boff = (size_t)(col0 + lrow) * K + k0 + lh * 8;
        cpasync16(base + 8192 + dOff,  Bth + boff, 16);
        cpasync16(base + 12288 + dOff, Btl + boff, 16);
    };

    const int a_r = lane & 15;
    const int a_h = lane >> 4;
    const int b_n = (lane & 7) + ((lane >> 4) << 3);
    const int b_h = (lane >> 3) & 1;

    load_tile(0, 0);
    cp_commit();
    if (KT > 1) { load_tile(1, 1); }
    cp_commit();

    int buf = 0;
    for (int kt = 0; kt < KT; kt++) {
        cp_wait1();
        __syncthreads();
        const uint32_t base = smemBase + buf * STAGEB;

        uint32_t ah[4][4], al[4][4], bh[4][2], bl[4][2];
#pragma unroll
        for (int mf = 0; mf < 4; mf++) {
            uint32_t ao = swz((uint32_t)((wm * 64 + mf * 16 + a_r) * 32 + a_h * 16));
            ldsm4(ah[mf], base + ao);
            ldsm4(al[mf], base + 4096 + ao);
        }
#pragma unroll
        for (int nf2 = 0; nf2 < 2; nf2++) {
            uint32_t bo = swz((uint32_t)((wn * 32 + nf2 * 16 + b_n) * 32 + b_h * 16));
            uint32_t t4[4];
            ldsm4(t4, base + 8192 + bo);
            bh[2 * nf2][0] = t4[0]; bh[2 * nf2][1] = t4[1];
            bh[2 * nf2 + 1][0] = t4[2]; bh[2 * nf2 + 1][1] = t4[3];
            ldsm4(t4, base + 12288 + bo);
            bl[2 * nf2][0] = t4[0]; bl[2 * nf2][1] = t4[1];
            bl[2 * nf2 + 1][0] = t4[2]; bl[2 * nf2 + 1][1] = t4[3];
        }
        // term-major: all 16 (mf,nf) tiles per term -> 16 independent acc
        // chains between accumulator reuses (asm volatile preserves order)
#pragma unroll
        for (int mf = 0; mf < 4; mf++)
#pragma unroll
            for (int nf = 0; nf < 4; nf++)
                mma_bf16(acc[mf][nf], ah[mf], bh[nf]);
#pragma unroll
        for (int mf = 0; mf < 4; mf++)
#pragma unroll
            for (int nf = 0; nf < 4; nf++)
                mma_bf16(acc[mf][nf], ah[mf], bl[nf]);
#pragma unroll
        for (int mf = 0; mf < 4; mf++)
#pragma unroll
            for (int nf = 0; nf < 4; nf++)
                mma_bf16(acc[mf][nf], al[mf], bh[nf]);

        if (kt + 2 < KT) {
            int nbuf = buf + 2; if (nbuf >= 3) nbuf -= 3;
            load_tile(kt + 2, nbuf);
        }
        cp_commit();
        if (++buf == 3) buf = 0;
    }
    __syncthreads();

    if (!LSTM) {
#pragma unroll
        for (int mf = 0; mf < 4; mf++) {
            int gr = row0 + wm * 64 + mf * 16 + (lane >> 2);
#pragma unroll
            for (int nf = 0; nf < 4; nf++) {
                int gc = col0 + wn * 32 + nf * 8 + 2 * (lane & 3);
                float b0 = bias[gc], b1 = bias[gc + 1];
                if (gr < M) {
                    float2 v = make_float2(acc[mf][nf][0] + b0, acc[mf][nf][1] + b1);
                    *(float2*)(Cout + (size_t)gr * Nt + gc) = v;
                }
                if (gr + 8 < M) {
                    float2 v = make_float2(acc[mf][nf][2] + b0, acc[mf][nf][3] + b1);
                    *(float2*)(Cout + (size_t)(gr + 8) * Nt + gc) = v;
                }
            }
        }
    } else {
        // gate quads interleaved: col 4j+{i,f,g,o}; stage 64-row chunks in smem
        float (*sC)[132] = (float (*)[132])smemc;
        const int j0 = col0 >> 2;
        for (int ch = 0; ch < 2; ch++) {
            __syncthreads();
            if (wm == ch) {
#pragma unroll
                for (int mf = 0; mf < 4; mf++) {
                    int rl = mf * 16 + (lane >> 2);
#pragma unroll
                    for (int nf = 0; nf < 4; nf++) {
                        int cl = wn * 32 + nf * 8 + 2 * (lane & 3);
                        float b0 = bias[col0 + cl], b1 = bias[col0 + cl + 1];
                        sC[rl][cl] = acc[mf][nf][0] + b0;
                        sC[rl][cl + 1] = acc[mf][nf][1] + b1;
                        sC[rl + 8][cl] = acc[mf][nf][2] + b0;
                        sC[rl + 8][cl + 1] = acc[mf][nf][3] + b1;
                    }
                }
            }
            __syncthreads();
            for (int q = tid; q < 64 * 32; q += 256) {
                int rl = q >> 5, jl = q & 31;
                int node = row0 + ch * 64 + rl;
                if (node < M) {
                    float4 g4 = *(float4*)&sC[rl][4 * jl];
                    size_t ci = (size_t)node * HH + j0 + jl;
                    float cn = sigm(g4.y) * cstate[ci] + sigm(g4.x) * tanhf(g4.z);
                    cstate[ci] = cn;
                    float hv = sigm(g4.w) * tanhf(cn);
                    if (hout) hout[ci] = hv;
                    split_bf16(hv, houth[ci], houtl[ci]);
                }
            }
        }
    }
}

// warp per node: out = h2 . out_w + out_b, h2 reconstructed from bf16 hi/lo planes
__global__ void out_proj_kernel(const __nv_bfloat16* __restrict__ h2h,
                                const __nv_bfloat16* __restrict__ h2l,
                                const float* __restrict__ w,
                                const float* __restrict__ b, float* __restrict__ out, int n) {
    int gw = (blockIdx.x * blockDim.x + threadIdx.x) >> 5;
    int lane = threadIdx.x & 31;
    if (gw >= n) return;
    // 4 elems per lane: 2x bf16x2 from each plane
    const __nv_bfloat162* ph = (const __nv_bfloat162*)(h2h + (size_t)gw * HH + lane * 4);
    const __nv_bfloat162* pl = (const __nv_bfloat162*)(h2l + (size_t)gw * HH + lane * 4);
    __nv_bfloat162 hh0 = ph[0], hh1 = ph[1], ll0 = pl[0], ll1 = pl[1];
    float4 wv = ((const float4*)w)[lane];
    float v0 = __bfloat162float(hh0.x) + __bfloat162float(ll0.x);
    float v1 = __bfloat162float(hh0.y) + __bfloat162float(ll0.y);
    float v2 = __bfloat162float(hh1.x) + __bfloat162float(ll1.x);
    float v3 = __bfloat162float(hh1.y) + __bfloat162float(ll1.y);
    float s = v0 * wv.x + v1 * wv.y + v2 * wv.z + v3 * wv.w;
#pragma unroll
    for (int off = 16; off; off >>= 1) s += __shfl_xor_sync(0xFFFFFFFFu, s, off);
    if (lane == 0) out[gw] = s + b[0];
}

__global__ void copy_states_kernel(const float* __restrict__ st, float* __restrict__ out, size_t nh) {
    size_t i = (size_t)blockIdx.x * blockDim.x + threadIdx.x;
    size_t total = 4 * nh;
    for (; i < total; i += (size_t)gridDim.x * blockDim.x) out[i] = st[i];
}

// ---------------- host launch ----------------
static inline int cdiv(int a, int b) { return (a + b - 1) / b; }
#define SYM(var, sym) cudaGetSymbolAddress((void**)&var, sym)

extern "C" void kernel_launch(void* const* d_in, const int* in_sizes, int n_in,
                              void* d_out, int out_size) {
    const float* x    = (const float*)d_in[0];
    const void*  ei   = d_in[1];
    const float* gw1  = (const float*)d_in[2];
    const float* gb1  = (const float*)d_in[3];
    const float* gw2  = (const float*)d_in[4];
    const float* gb2  = (const float*)d_in[5];
    const float* wih1 = (const float*)d_in[6];
    const float* whh1 = (const float*)d_in[7];
    const float* bih1 = (const float*)d_in[8];
    const float* bhh1 = (const float*)d_in[9];
    const float* wih2 = (const float*)d_in[10];
    const float* whh2 = (const float*)d_in[11];
    const float* bih2 = (const float*)d_in[12];
    const float* bhh2 = (const float*)d_in[13];
    const float* outw = (const float*)d_in[14];
    const float* outb = (const float*)d_in[15];

    const int N = in_sizes[0] / (TT * FIN);
    const int E = in_sizes[1] / (2 * TT);
    float* out = (float*)d_out;

    __nv_bfloat16 *xh, *xl, *fh, *fl, *b2h, *b2l;
    __nv_bfloat16 *h1h_a, *h1l_a, *h1h_b, *h1l_b, *h2h_a, *h2l_a, *h2h_b, *h2l_b;
    __nv_bfloat16 *B1h, *B1l, *B2h, *B2l, *GW1h, *GW1l, *GW2h, *GW2l;
    float *nis, *hlin, *state, *bias1, *bias2;
    int *offs, *cursor, *csr;
    SYM(xh, g_xh); SYM(xl, g_xl); SYM(fh, g_fh); SYM(fl, g_fl);
    SYM(b2h, g_b2h); SYM(b2l, g_b2l);
    SYM(h1h_a, g_h1h_a); SYM(h1l_a, g_h1l_a); SYM(h1h_b, g_h1h_b); SYM(h1l_b, g_h1l_b);
    SYM(h2h_a, g_h2h_a); SYM(h2l_a, g_h2l_a); SYM(h2h_b, g_h2h_b); SYM(h2l_b, g_h2l_b);
    SYM(B1h, g_B1h); SYM(B1l, g_B1l); SYM(B2h, g_B2h); SYM(B2l, g_B2l);
    SYM(GW1h, g_GW1h); SYM(GW1l, g_GW1l); SYM(GW2h, g_GW2h); SYM(GW2l, g_GW2l);
    SYM(nis, g_nis); SYM(hlin, g_hlin);
    SYM(offs, g_offs); SYM(cursor, g_cursor); SYM(csr, g_csr);
    SYM(state, g_state); SYM(bias1, g_bias1); SYM(bias2, g_bias2);

    const size_t NH = (size_t)N * HH;
    const long long TN = (long long)TT * N;

    const int mbA = (int)((TN + BM - 1) / BM);  // 3125
    const int mbL = cdiv(N, BM);                // 391

    // launch order keeps GCN L1 GEMM at #5 (ncu sentinel across rounds)
    detect_idx_kernel<<<1, 1>>>(ei);                                            // 1
    prep_weights_kernel<<<cdiv(512 * 256, 256), 256>>>(gw1, gw2, wih1, whh1,    // 2
                                                       bih1, bhh1, wih2, whh2, bih2, bhh2);
    split_x_kernel<<<2048, 256>>>(x, (size_t)TN * FIN);                         // 3
    cudaMemsetAsync(nis, 0, TN * sizeof(float));                                // 4

    // -------- GCN layer 1 GEMM (batched over all t) --------                  // 5
    mma_gemm_kernel<false><<<dim3(1, mbA), 256>>>(
        (int)TN, HH, 128, xh, xl, nullptr, nullptr, GW1h, GW1l, gb1,
        hlin, nullptr, nullptr, nullptr, nullptr);

    // -------- degrees -> CSR offsets -> fill -> nis --------
    deg_all_kernel<<<(unsigned)(((long long)TT * E + 255) / 256), 256>>>(ei, E, N, nis);
    scan_offsets_kernel<<<TT, 1024>>>(nis, offs, N);
    cudaMemsetAsync(cursor, 0, (size_t)TT * N * sizeof(int));
    csr_fill_kernel<<<(unsigned)(((long long)TT * E + 255) / 256), 256>>>(ei, E, N, offs, cursor, csr);
    nis_all_kernel<<<(unsigned)((TN + 255) / 256), 256>>>(nis, TN);

    // -------- GCN layer 1 gather (per-t; fused combine+relu+split) --------
    for (int t = 0; t < TT; t++) {
        gather_combine_kernel<<<cdiv(N * 32, 256), 256>>>(
            csr + (size_t)t * E, offs + (size_t)t * (N + 1),
            nis + (size_t)t * N, hlin + (size_t)t * NH,
            b2h + (size_t)t * NH, b2l + (size_t)t * NH, N);
    }

    // -------- GCN layer 2 --------
    mma_gemm_kernel<false><<<dim3(1, mbA), 256>>>(
        (int)TN, HH, 128, b2h, b2l, nullptr, nullptr, GW2h, GW2l, gb2,
        hlin, nullptr, nullptr, nullptr, nullptr);
    for (int t = 0; t < TT; t++) {
        gather_combine_kernel<<<cdiv(N * 32, 256), 256>>>(
            csr + (size_t)t * E, offs + (size_t)t * (N + 1),
            nis + (size_t)t * N, hlin + (size_t)t * NH,
            fh + (size_t)t * NH, fl + (size_t)t * NH, N);
    }

    // -------- LSTM over time (fused gates+cell GEMM, ping-pong h planes) -----
    cudaMemsetAsync(state, 0, 4 * NH * sizeof(float));
    cudaMemsetAsync(h1h_a, 0, NH * sizeof(__nv_bfloat16));
    cudaMemsetAsync(h1l_a, 0, NH * sizeof(__nv_bfloat16));
    cudaMemsetAsync(h2h_a, 0, NH * sizeof(__nv_bfloat16));
    cudaMemsetAsync(h2l_a, 0, NH * sizeof(__nv_bfloat16));

    float* h1a = state;               // final h1 (t=7 odd writes A bufs)
    float* c1  = state + NH;
    float* h2a = state + 2 * NH;
    float* c2  = state + 3 * NH;

    for (int t = 0; t < TT; t++) {
        const int odd = t & 1;
        const __nv_bfloat16* h1ih = odd ? h1h_b : h1h_a;
        const __nv_bfloat16* h1il = odd ? h1l_b : h1l_a;
        __nv_bfloat16* h1oh = odd ? h1h_a : h1h_b;
        __nv_bfloat16* h1ol = odd ? h1l_a : h1l_b;
        const __nv_bfloat16* h2ih = odd ? h2h_b : h2h_a;
        const __nv_bfloat16* h2il = odd ? h2l_b : h2l_a;
        __nv_bfloat16* h2oh = odd ? h2h_a : h2h_b;
        __nv_bfloat16* h2ol = odd ? h2l_a : h2l_b;
        float* h1_out = (t == TT - 1) ? h1a : nullptr;   // fp32 h1 only at the end
        float* h2_out = (t == TT - 1) ? h2a : nullptr;   // fp32 h2 only at the end

        // layer 1: K=256 [feats_t ; h1_{t-1}]
        mma_gemm_kernel<true><<<dim3(4, mbL), 256>>>(
            N, G4, 256, fh + (size_t)t * NH, fl + (size_t)t * NH, h1ih, h1il,
            B1h, B1l, bias1, nullptr, c1, h1_out, h1oh, h1ol);
        // layer 2: K=256 [h1_t ; h2_{t-1}]
        mma_gemm_kernel<true><<<dim3(4, mbL), 256>>>(
            N, G4, 256, h1oh, h1ol, h2ih, h2il,
            B2h, B2l, bias2, nullptr, c2, h2_out, h2oh, h2ol);
        // out_proj from bf16 planes (skips fp32 h2 round-trip)
        out_proj_kernel<<<cdiv(N * 32, 256), 256>>>(h2oh, h2ol, outw, outb,
                                                    out + (size_t)t * N, N);
    }

    // -------- tail: h1, c1, h2, c2 (t=7 odd -> finals in buf A = state) ------
    copy_states_kernel<<<1024, 256>>>(state, out + (size_t)TT * N, NH);
}